// round 8
// baseline (speedup 1.0000x reference)
#include <cuda_runtime.h>
#include <cuda_bf16.h>
#include <stdint.h>
#include <math.h>

// Problem constants
#define Nn    50000
#define Mpad  50048
#define Ee    800000
#define FEAT  512
#define HEADS 8
#define HID   64
#define C1    512
#define NC    64
#define ALPHA 0.2f

// ---------------- scratch -----------------------------------------------------
__device__ float g_Wh [(size_t)Nn * C1];
__device__ float g_Wh2[(size_t)Nn * NC];
__device__ float g_fd1[Nn * HEADS];
__device__ float g_fs1[Nn * HEADS];
__device__ float g_fd2[Nn];
__device__ float g_fs2[Nn];
__device__ float g_lg1[(size_t)Ee * HEADS]; // CSR-ordered raw logits
__device__ float g_lg2[Ee];                 // CSR-ordered raw logits
__device__ int   g_cnt[Nn];
__device__ int   g_off[Nn + 1];
__device__ int   g_cur[Nn];
__device__ int   g_pos [Ee];   // edge e -> CSR slot p
__device__ int   g_cols[Ee];   // CSR slot p -> src node

// bf16 hi/lo operands (weights + h1 only; x converted in-kernel now)
__device__ __align__(256) __nv_bfloat16 g_bhi[512 * 512];
__device__ __align__(256) __nv_bfloat16 g_blo[512 * 512];
__device__ __align__(256) __nv_bfloat16 g_h1hi[(size_t)Mpad * 512];  // pad rows stay 0
__device__ __align__(256) __nv_bfloat16 g_h1lo[(size_t)Mpad * 512];
__device__ __align__(256) __nv_bfloat16 g_b2hi[64 * 512];
__device__ __align__(256) __nv_bfloat16 g_b2lo[64 * 512];

// ---------------- PTX helpers --------------------------------------------------
__device__ __forceinline__ uint32_t smem_u32(const void* p) {
    uint32_t a;
    asm("{ .reg .u64 t; cvta.to.shared.u64 t, %1; cvt.u32.u64 %0, t; }" : "=r"(a) : "l"(p));
    return a;
}
__device__ __forceinline__ void cpa16(uint32_t dst, const void* src) {
    asm volatile("cp.async.cg.shared.global [%0], [%1], 16;" :: "r"(dst), "l"(src));
}
__device__ __forceinline__ void cpa_commit() {
    asm volatile("cp.async.commit_group;" ::: "memory");
}
template <int N> __device__ __forceinline__ void cpa_wait() {
    asm volatile("cp.async.wait_group %0;" :: "n"(N) : "memory");
}
__device__ __forceinline__ void ldm4(uint32_t* r, uint32_t addr) {
    asm volatile("ldmatrix.sync.aligned.m8n8.x4.shared.b16 {%0,%1,%2,%3}, [%4];"
                 : "=r"(r[0]), "=r"(r[1]), "=r"(r[2]), "=r"(r[3]) : "r"(addr));
}
__device__ __forceinline__ void mma16816(float* c, const uint32_t* a,
                                         uint32_t b0, uint32_t b1) {
    asm volatile(
        "mma.sync.aligned.m16n8k16.row.col.f32.bf16.bf16.f32 "
        "{%0,%1,%2,%3}, {%4,%5,%6,%7}, {%8,%9}, {%0,%1,%2,%3};"
        : "+f"(c[0]), "+f"(c[1]), "+f"(c[2]), "+f"(c[3])
        : "r"(a[0]), "r"(a[1]), "r"(a[2]), "r"(a[3]), "r"(b0), "r"(b1));
}

// ---------------- weight conversion kernels ------------------------------------
__global__ void k_cvt_w(const float* __restrict__ W) {
    int idx = blockIdx.x * blockDim.x + threadIdx.x;
    if (idx >= 512 * 512) return;
    int n = idx >> 9, k = idx & 511;
    float v = W[(size_t)(n >> 6) * (512 * 64) + (size_t)k * 64 + (n & 63)];
    __nv_bfloat16 h = __float2bfloat16_rn(v);
    __nv_bfloat16 l = __float2bfloat16_rn(v - __bfloat162float(h));
    g_bhi[idx] = h;
    g_blo[idx] = l;
}

__global__ void k_cvt_w2(const float* __restrict__ W_out) {
    int idx = blockIdx.x * blockDim.x + threadIdx.x;
    if (idx >= 64 * 512) return;
    int n = idx >> 9, k = idx & 511;
    float v = W_out[(size_t)k * 64 + n];
    __nv_bfloat16 h = __float2bfloat16_rn(v);
    __nv_bfloat16 l = __float2bfloat16_rn(v - __bfloat162float(h));
    g_b2hi[idx] = h;
    g_b2lo[idx] = l;
}

// ---------------- HMMA GEMM1 (in-kernel x conversion, +f1 epilogue) ------------
#define A_HI 0
#define A_LO 10240
#define B_HI 20480
#define B_LO 30720
#define STAGE 40960
#define SMEM_GEMM_TOTAL (2 * STAGE)

__device__ __forceinline__ void ldb(uint32_t s, int t, int n0, int kc) {
    int k0 = kc * 32;
#pragma unroll
    for (int i = 0; i < 2; i++) {
        int idx = t + i * 256;
        int r = idx >> 2, c = idx & 3;
        uint32_t d = s + (uint32_t)(r * 80 + c * 16);
        size_t sbg = (size_t)(n0 + r) * 512 + k0 + c * 8;
        cpa16(d + B_HI, g_bhi + sbg);
        cpa16(d + B_LO, g_blo + sbg);
    }
    cpa_commit();
}

__device__ __forceinline__ void cvt_sts(char* stage, uint32_t a_sts, const float4* xv) {
    uint32_t hbuf[8], lbuf[8];
    const float* f = (const float*)xv;
#pragma unroll
    for (int i = 0; i < 8; i++) {
        float a0 = f[2 * i], b0 = f[2 * i + 1];
        __nv_bfloat162 hp, lp;
        hp.x = __float2bfloat16_rn(a0);
        hp.y = __float2bfloat16_rn(b0);
        lp.x = __float2bfloat16_rn(a0 - __bfloat162float(hp.x));
        lp.y = __float2bfloat16_rn(b0 - __bfloat162float(hp.y));
        hbuf[i] = *(uint32_t*)&hp;
        lbuf[i] = *(uint32_t*)&lp;
    }
    *(uint4*)(stage + A_HI + a_sts)      = make_uint4(hbuf[0], hbuf[1], hbuf[2], hbuf[3]);
    *(uint4*)(stage + A_HI + a_sts + 16) = make_uint4(hbuf[4], hbuf[5], hbuf[6], hbuf[7]);
    *(uint4*)(stage + A_LO + a_sts)      = make_uint4(lbuf[0], lbuf[1], lbuf[2], lbuf[3]);
    *(uint4*)(stage + A_LO + a_sts + 16) = make_uint4(lbuf[4], lbuf[5], lbuf[6], lbuf[7]);
}

__global__ void __launch_bounds__(256) k_gemm1_mma(const float* __restrict__ x,
                                                   const float* __restrict__ a_vec) {
    extern __shared__ char smem[];
    __shared__ float s_ad[2][64], s_as[2][64];
    uint32_t sb = smem_u32(smem);
    const int t = threadIdx.x;
    const int lane = t & 31, w = t >> 5;
    const int wm = w & 3, wn = w >> 2;
    const int m0 = blockIdx.x * 128, n0 = blockIdx.y * 128;

    if (t < 128) {
        int hh = t >> 6, j = t & 63;
        int gh = blockIdx.y * 2 + hh;
        s_ad[hh][j] = a_vec[gh * 128 + j];
        s_as[hh][j] = a_vec[gh * 128 + 64 + j];
    }

    float acc[2][8][4];
#pragma unroll
    for (int mf = 0; mf < 2; mf++)
#pragma unroll
        for (int nf = 0; nf < 8; nf++)
#pragma unroll
            for (int q = 0; q < 4; q++) acc[mf][nf][q] = 0.f;

    // A register staging geometry: 2 threads/row, 16 fp32 cols each
    const int ar = t >> 1;
    const int ac = (t & 1) * 16;
    const bool a_ok = (m0 + ar) < Nn;
    const float* a_src = x + (size_t)(m0 + ar) * 512 + ac;
    const uint32_t a_sts = (uint32_t)(ar * 80 + ac * 2);
    const float4 fz = make_float4(0.f, 0.f, 0.f, 0.f);

    // prologue: stage 0
    {
        float4 xv[4];
#pragma unroll
        for (int j2 = 0; j2 < 4; j2++)
            xv[j2] = a_ok ? *(const float4*)(a_src + j2 * 4) : fz;
        cvt_sts(smem, a_sts, xv);
    }
    ldb(sb, t, n0, 0);
    cpa_wait<0>();
    __syncthreads();

    const int a_row = wm * 32 + (lane & 15);
    const int a_colb = (lane >> 4) * 8;
    const int b_row = wn * 64 + ((lane >> 4) & 1) * 8 + (lane & 7);
    const int b_colb = ((lane >> 3) & 1) * 8;

    for (int kc = 0; kc < 16; kc++) {
        uint32_t s = sb + (uint32_t)(kc & 1) * STAGE;
        char* sc_next = smem + (size_t)((kc + 1) & 1) * STAGE;

        float4 xv[4];
        if (kc + 1 < 16) {
            ldb(sb + (uint32_t)((kc + 1) & 1) * STAGE, t, n0, kc + 1);
            const float* srcn = a_src + (kc + 1) * 32;
#pragma unroll
            for (int j2 = 0; j2 < 4; j2++)
                xv[j2] = a_ok ? *(const float4*)(srcn + j2 * 4) : fz;
        }

#pragma unroll
        for (int ks = 0; ks < 2; ks++) {
            uint32_t ah[2][4], al[2][4];
#pragma unroll
            for (int mf = 0; mf < 2; mf++) {
                uint32_t ad = s + (uint32_t)((a_row + mf * 16) * 80 + (ks * 16 + a_colb) * 2);
                ldm4(ah[mf], ad + A_HI);
                ldm4(al[mf], ad + A_LO);
            }
            uint32_t bh[4][4], bl[4][4];
#pragma unroll
            for (int nb = 0; nb < 4; nb++) {
                uint32_t bd = s + (uint32_t)((b_row + nb * 16) * 80 + (ks * 16 + b_colb) * 2);
                ldm4(bh[nb], bd + B_HI);
                ldm4(bl[nb], bd + B_LO);
            }
#pragma unroll
            for (int mf = 0; mf < 2; mf++)
#pragma unroll
                for (int nb = 0; nb < 4; nb++)
#pragma unroll
                    for (int half = 0; half < 2; half++) {
                        float* c = acc[mf][nb * 2 + half];
                        mma16816(c, ah[mf], bh[nb][half * 2], bh[nb][half * 2 + 1]);
                        mma16816(c, ah[mf], bl[nb][half * 2], bl[nb][half * 2 + 1]);
                        mma16816(c, al[mf], bh[nb][half * 2], bh[nb][half * 2 + 1]);
                    }
        }

        if (kc + 1 < 16) {
            cvt_sts(sc_next, a_sts, xv);
            cpa_wait<0>();
        }
        __syncthreads();
    }

    // epilogue: store Wh + fused f1
    const int ghead = blockIdx.y * 2 + wn;
#pragma unroll
    for (int mf = 0; mf < 2; mf++) {
        int rbase = m0 + wm * 32 + mf * 16 + (lane >> 2);
#pragma unroll
        for (int nf = 0; nf < 8; nf++) {
            int cc = n0 + wn * 64 + nf * 8 + (lane & 3) * 2;
            float* c = acc[mf][nf];
            if (rbase < Nn)
                *(float2*)(g_Wh + (size_t)rbase * 512 + cc) = make_float2(c[0], c[1]);
            if (rbase + 8 < Nn)
                *(float2*)(g_Wh + (size_t)(rbase + 8) * 512 + cc) = make_float2(c[2], c[3]);
        }
#pragma unroll
        for (int half = 0; half < 2; half++) {
            float pd = 0.f, ps = 0.f;
#pragma unroll
            for (int nf = 0; nf < 8; nf++) {
                int j0 = nf * 8 + (lane & 3) * 2;
                float c0 = acc[mf][nf][half * 2 + 0];
                float c1 = acc[mf][nf][half * 2 + 1];
                pd += c0 * s_ad[wn][j0] + c1 * s_ad[wn][j0 + 1];
                ps += c0 * s_as[wn][j0] + c1 * s_as[wn][j0 + 1];
            }
            pd += __shfl_xor_sync(0xffffffffu, pd, 1);
            pd += __shfl_xor_sync(0xffffffffu, pd, 2);
            ps += __shfl_xor_sync(0xffffffffu, ps, 1);
            ps += __shfl_xor_sync(0xffffffffu, ps, 2);
            int r = rbase + half * 8;
            if ((lane & 3) == 0 && r < Nn) {
                g_fd1[r * 8 + ghead] = pd;
                g_fs1[r * 8 + ghead] = ps;
            }
        }
    }
}

// ---------------- HMMA GEMM2 (+f2 epilogue) -----------------------------------
#define A2_HI 0
#define A2_LO 10240
#define B2_HI 20480
#define B2_LO 25600
#define STAGE2 30720
#define SMEM_GEMM2_TOTAL (2 * STAGE2)

__device__ __forceinline__ void load_stage2(uint32_t s, int t, int m0, int kc) {
    int k0 = kc * 32;
#pragma unroll
    for (int i = 0; i < 2; i++) {
        int idx = t + i * 256;
        int r = idx >> 2;
        int c = idx & 3;
        uint32_t d = s + (uint32_t)(r * 80 + c * 16);
        size_t sa = (size_t)(m0 + r) * 512 + k0 + c * 8;
        cpa16(d + A2_HI, g_h1hi + sa);
        cpa16(d + A2_LO, g_h1lo + sa);
    }
    if (t < 256) {
        int r = t >> 2, c = t & 3;
        uint32_t d = s + (uint32_t)(r * 80 + c * 16);
        size_t sbg = (size_t)r * 512 + k0 + c * 8;
        cpa16(d + B2_HI, g_b2hi + sbg);
        cpa16(d + B2_LO, g_b2lo + sbg);
    }
    cpa_commit();
}

__global__ void __launch_bounds__(256) k_gemm2_mma(const float* __restrict__ a_out) {
    extern __shared__ char smem[];
    __shared__ float s_a2d[64], s_a2s[64];
    __shared__ float s_pd[2][128], s_ps[2][128];
    uint32_t sb = smem_u32(smem);
    const int t = threadIdx.x;
    const int lane = t & 31, w = t >> 5;
    const int wm = w & 3, wn = w >> 2;
    const int m0 = blockIdx.x * 128;

    if (t < 64) {
        s_a2d[t] = a_out[t];
        s_a2s[t] = a_out[64 + t];
    }

    float acc[2][4][4];
#pragma unroll
    for (int mf = 0; mf < 2; mf++)
#pragma unroll
        for (int nf = 0; nf < 4; nf++)
#pragma unroll
            for (int q = 0; q < 4; q++) acc[mf][nf][q] = 0.f;

    load_stage2(sb, t, m0, 0);

    const int a_row = wm * 32 + (lane & 15);
    const int a_colb = (lane >> 4) * 8;
    const int b_row = wn * 32 + ((lane >> 4) & 1) * 8 + (lane & 7);
    const int b_colb = ((lane >> 3) & 1) * 8;

    for (int kc = 0; kc < 16; kc++) {
        uint32_t s = sb + (uint32_t)(kc & 1) * STAGE2;
        if (kc + 1 < 16) load_stage2(sb + (uint32_t)((kc + 1) & 1) * STAGE2, t, m0, kc + 1);
        if (kc + 1 < 16) { cpa_wait<1>(); } else { cpa_wait<0>(); }
        __syncthreads();

#pragma unroll
        for (int ks = 0; ks < 2; ks++) {
            uint32_t ah[2][4], al[2][4];
#pragma unroll
            for (int mf = 0; mf < 2; mf++) {
                uint32_t ad = s + (uint32_t)((a_row + mf * 16) * 80 + (ks * 16 + a_colb) * 2);
                ldm4(ah[mf], ad + A2_HI);
                ldm4(al[mf], ad + A2_LO);
            }
            uint32_t bh[2][4], bl[2][4];
#pragma unroll
            for (int nb = 0; nb < 2; nb++) {
                uint32_t bd = s + (uint32_t)((b_row + nb * 16) * 80 + (ks * 16 + b_colb) * 2);
                ldm4(bh[nb], bd + B2_HI);
                ldm4(bl[nb], bd + B2_LO);
            }
#pragma unroll
            for (int mf = 0; mf < 2; mf++)
#pragma unroll
                for (int nb = 0; nb < 2; nb++)
#pragma unroll
                    for (int half = 0; half < 2; half++) {
                        float* c = acc[mf][nb * 2 + half];
                        mma16816(c, ah[mf], bh[nb][half * 2], bh[nb][half * 2 + 1]);
                        mma16816(c, ah[mf], bl[nb][half * 2], bl[nb][half * 2 + 1]);
                        mma16816(c, al[mf], bh[nb][half * 2], bh[nb][half * 2 + 1]);
                    }
        }
        __syncthreads();
    }

#pragma unroll
    for (int mf = 0; mf < 2; mf++) {
        int rbase = m0 + wm * 32 + mf * 16 + (lane >> 2);
#pragma unroll
        for (int nf = 0; nf < 4; nf++) {
            int cc = wn * 32 + nf * 8 + (lane & 3) * 2;
            float* c = acc[mf][nf];
            if (rbase < Nn)
                *(float2*)(g_Wh2 + (size_t)rbase * 64 + cc) = make_float2(c[0], c[1]);
            if (rbase + 8 < Nn)
                *(float2*)(g_Wh2 + (size_t)(rbase + 8) * 64 + cc) = make_float2(c[2], c[3]);
        }
#pragma unroll
        for (int half = 0; half < 2; half++) {
            float pd = 0.f, ps = 0.f;
#pragma unroll
            for (int nf = 0; nf < 4; nf++) {
                int j0 = wn * 32 + nf * 8 + (lane & 3) * 2;
                float c0 = acc[mf][nf][half * 2 + 0];
                float c1 = acc[mf][nf][half * 2 + 1];
                pd += c0 * s_a2d[j0] + c1 * s_a2d[j0 + 1];
                ps += c0 * s_a2s[j0] + c1 * s_a2s[j0 + 1];
            }
            pd += __shfl_xor_sync(0xffffffffu, pd, 1);
            pd += __shfl_xor_sync(0xffffffffu, pd, 2);
            ps += __shfl_xor_sync(0xffffffffu, ps, 1);
            ps += __shfl_xor_sync(0xffffffffu, ps, 2);
            int rl = wm * 32 + mf * 16 + (lane >> 2) + half * 8;
            if ((lane & 3) == 0) {
                s_pd[wn][rl] = pd;
                s_ps[wn][rl] = ps;
            }
        }
    }
    __syncthreads();
    if (t < 128) {
        int r = m0 + t;
        if (r < Nn) {
            g_fd2[r] = s_pd[0][t] + s_pd[1][t];
            g_fs2[r] = s_ps[0][t] + s_ps[1][t];
        }
    }
}

// ---------------- CSR build ------------------------------------------------
__global__ void k_zero_cnt() {
    int i = blockIdx.x * blockDim.x + threadIdx.x;
    if (i < Nn) g_cnt[i] = 0;
}

__global__ void k_hist(const int* __restrict__ row) {
    int e = blockIdx.x * blockDim.x + threadIdx.x;
    if (e < Ee) atomicAdd(&g_cnt[row[e]], 1);
}

__global__ void k_scan() {   // 1024 threads, shfl-based
    __shared__ int s_w[32];
    __shared__ int s_base, s_next;
    int t = threadIdx.x, lane = t & 31, wid = t >> 5;
    if (t == 0) s_base = 0;
    __syncthreads();
    for (int start = 0; start < Nn; start += 1024) {
        int i = start + t;
        int v = (i < Nn) ? g_cnt[i] : 0;
        int sc = v;
#pragma unroll
        for (int d = 1; d < 32; d <<= 1) {
            int u = __shfl_up_sync(0xffffffffu, sc, d);
            if (lane >= d) sc += u;
        }
        if (lane == 31) s_w[wid] = sc;
        __syncthreads();
        if (wid == 0) {
            int wsc = s_w[lane];
#pragma unroll
            for (int d = 1; d < 32; d <<= 1) {
                int u = __shfl_up_sync(0xffffffffu, wsc, d);
                if (lane >= d) wsc += u;
            }
            s_w[lane] = wsc;
            if (lane == 31) s_next = wsc;
        }
        __syncthreads();
        int base = s_base;
        int warpoff = (wid == 0) ? 0 : s_w[wid - 1];
        int ex = base + warpoff + sc - v;
        if (i < Nn) { g_off[i] = ex; g_cur[i] = ex; }
        __syncthreads();
        if (t == 0) s_base = base + s_next;
        __syncthreads();
    }
    if (t == 0) g_off[Nn] = s_base;
}

__global__ void k_scatter(const int* __restrict__ row, const int* __restrict__ col) {
    int e = blockIdx.x * blockDim.x + threadIdx.x;
    if (e < Ee) {
        int r = row[e];
        int p = atomicAdd(&g_cur[r], 1);
        g_pos[e]  = p;
        g_cols[p] = col[e];
    }
}

// ---------------- layer1: edge logits -> CSR slots --------------------------
__global__ void k_logits1(const int* __restrict__ row, const int* __restrict__ col) {
    int e = blockIdx.x * blockDim.x + threadIdx.x;
    if (e >= Ee) return;
    int r = row[e], c = col[e];
    float4 d0 = *(const float4*)(g_fd1 + r * 8);
    float4 d1 = *(const float4*)(g_fd1 + r * 8 + 4);
    float4 s0 = *(const float4*)(g_fs1 + c * 8);
    float4 s1 = *(const float4*)(g_fs1 + c * 8 + 4);
    float v[8] = {d0.x + s0.x, d0.y + s0.y, d0.z + s0.z, d0.w + s0.w,
                  d1.x + s1.x, d1.y + s1.y, d1.z + s1.z, d1.w + s1.w};
#pragma unroll
    for (int h = 0; h < 8; h++) v[h] = v[h] > 0.f ? v[h] : ALPHA * v[h];
    size_t p = (size_t)g_pos[e] * 8;
    *(float4*)(g_lg1 + p)     = make_float4(v[0], v[1], v[2], v[3]);
    *(float4*)(g_lg1 + p + 4) = make_float4(v[4], v[5], v[6], v[7]);
}

// ---------------- layer1: fused softmax stats + aggregation + ELU ------------
__global__ void __launch_bounds__(256) k_agg1() {
    int i = blockIdx.x;
    int t = threadIdx.x;
    int o = g_off[i], oe = g_off[i + 1];
    __shared__ float s_red[32][8];
    __shared__ float s_mx[8], s_iv[8];
    __shared__ float s_att[32][8];
    __shared__ int   s_col[32];
    int j = t >> 3, h = t & 7;

    // pass 1: max per head
    float mx = -3.4e38f;
    for (int p = o + j; p < oe; p += 32)
        mx = fmaxf(mx, g_lg1[(size_t)p * 8 + h]);
    s_red[j][h] = mx;
    __syncthreads();
#pragma unroll
    for (int s = 16; s > 0; s >>= 1) {
        if (j < s) s_red[j][h] = fmaxf(s_red[j][h], s_red[j + s][h]);
        __syncthreads();
    }
    float mxh = s_red[0][h];
    __syncthreads();
    // pass 2: sum of exp
    float sm = 0.f;
    for (int p = o + j; p < oe; p += 32)
        sm += __expf(g_lg1[(size_t)p * 8 + h] - mxh);
    s_red[j][h] = sm;
    __syncthreads();
#pragma unroll
    for (int s = 16; s > 0; s >>= 1) {
        if (j < s) s_red[j][h] += s_red[j + s][h];
        __syncthreads();
    }
    if (j == 0) {
        s_mx[h] = (oe > o) ? mxh : 0.f;
        s_iv[h] = (oe > o) ? 1.f / fmaxf(s_red[0][h], 1e-16f) : 0.f;
    }
    __syncthreads();

    int ha = t >> 6;
    int hb = ha + 4;
    float acc0 = 0.f, acc1 = 0.f;
    for (int base = o; base < oe; base += 32) {
        int cnt = min(32, oe - base);
        __syncthreads();
        if (j < cnt)
            s_att[j][h] = __expf(g_lg1[(size_t)(base + j) * 8 + h] - s_mx[h]) * s_iv[h];
        if (t < cnt) s_col[t] = g_cols[base + t];
        __syncthreads();
        for (int q = 0; q < cnt; q++) {
            int c = s_col[q];
            const float* whc = g_Wh + (size_t)c * 512;
            acc0 = fmaf(s_att[q][ha], whc[t], acc0);
            acc1 = fmaf(s_att[q][hb], whc[t + 256], acc1);
        }
    }
    float v0 = acc0 > 0.f ? acc0 : (__expf(acc0) - 1.f);
    float v1 = acc1 > 0.f ? acc1 : (__expf(acc1) - 1.f);
    size_t basew = (size_t)i * 512;
    __nv_bfloat16 h0 = __float2bfloat16_rn(v0);
    __nv_bfloat16 h1 = __float2bfloat16_rn(v1);
    g_h1hi[basew + t]       = h0;
    g_h1hi[basew + t + 256] = h1;
    g_h1lo[basew + t]       = __float2bfloat16_rn(v0 - __bfloat162float(h0));
    g_h1lo[basew + t + 256] = __float2bfloat16_rn(v1 - __bfloat162float(h1));
}

// ---------------- layer2: edge logits ---------------------------------------
__global__ void k_logits2(const int* __restrict__ row, const int* __restrict__ col) {
    int e = blockIdx.x * blockDim.x + threadIdx.x;
    if (e >= Ee) return;
    float v = g_fd2[row[e]] + g_fs2[col[e]];
    g_lg2[g_pos[e]] = v > 0.f ? v : ALPHA * v;
}

// ---------------- layer2: fused stats + aggregation --------------------------
__global__ void __launch_bounds__(64) k_agg2(float* __restrict__ out) {
    int i = blockIdx.x;
    int t = threadIdx.x;  // 64
    int o = g_off[i], oe = g_off[i + 1];
    __shared__ float s_r[64];
    __shared__ float s_att[64];
    __shared__ int   s_col[64];

    float mx = -3.4e38f;
    for (int p = o + t; p < oe; p += 64) mx = fmaxf(mx, g_lg2[p]);
    s_r[t] = mx;
    __syncthreads();
#pragma unroll
    for (int s = 32; s > 0; s >>= 1) {
        if (t < s) s_r[t] = fmaxf(s_r[t], s_r[t + s]);
        __syncthreads();
    }
    float M = s_r[0];
    __syncthreads();
    float sm = 0.f;
    for (int p = o + t; p < oe; p += 64) sm += __expf(g_lg2[p] - M);
    s_r[t] = sm;
    __syncthreads();
#pragma unroll
    for (int s = 32; s > 0; s >>= 1) {
        if (t < s) s_r[t] += s_r[t + s];
        __syncthreads();
    }
    float iv = (oe > o) ? 1.f / fmaxf(s_r[0], 1e-16f) : 0.f;
    __syncthreads();

    float acc = 0.f;
    for (int base = o; base < oe; base += 64) {
        int cnt = min(64, oe - base);
        __syncthreads();
        if (t < cnt) {
            s_att[t] = __expf(g_lg2[base + t] - M) * iv;
            s_col[t] = g_cols[base + t];
        }
        __syncthreads();
        for (int q = 0; q < cnt; q++)
            acc = fmaf(s_att[q], g_Wh2[(size_t)s_col[q] * 64 + t], acc);
    }
    out[(size_t)i * 64 + t] = acc;
}

// ---------------- launch -----------------------------------------------------
extern "C" void kernel_launch(void* const* d_in, const int* in_sizes, int n_in,
                              void* d_out, int out_size) {
    const float* x     = (const float*)d_in[0];
    const int*   row   = (const int*)  d_in[1];
    const int*   col   = (const int*)  d_in[2];
    const float* W     = (const float*)d_in[3];
    const float* a     = (const float*)d_in[4];
    const float* W_out = (const float*)d_in[5];
    const float* a_out = (const float*)d_in[6];
    float* out = (float*)d_out;

    const int EB = (Ee + 255) / 256;

    cudaFuncSetAttribute(k_gemm1_mma, cudaFuncAttributeMaxDynamicSharedMemorySize,
                         SMEM_GEMM_TOTAL);
    cudaFuncSetAttribute(k_gemm2_mma, cudaFuncAttributeMaxDynamicSharedMemorySize,
                         SMEM_GEMM2_TOTAL);

    k_cvt_w<<<(512 * 512 + 255) / 256, 256>>>(W);                          // 0
    k_cvt_w2<<<(64 * 512 + 255) / 256, 256>>>(W_out);                      // 1
    k_zero_cnt<<<(Nn + 255) / 256, 256>>>();                               // 2
    k_gemm1_mma<<<dim3(Mpad / 128, 4), 256, SMEM_GEMM_TOTAL>>>(x, a);      // 3 <- profiled
    k_hist<<<EB, 256>>>(row);                                              // 4
    k_scan<<<1, 1024>>>();                                                 // 5
    k_scatter<<<EB, 256>>>(row, col);                                      // 6
    k_logits1<<<EB, 256>>>(row, col);                                      // 7
    k_agg1<<<Nn, 256>>>();                                                 // 8
    k_gemm2_mma<<<Mpad / 128, 256, SMEM_GEMM2_TOTAL>>>(a_out);             // 9
    k_logits2<<<EB, 256>>>(row, col);                                      // 10
    k_agg2<<<Nn, 64>>>(out);                                               // 11
}

// round 9
// speedup vs baseline: 1.0453x; 1.0453x over previous
#include <cuda_runtime.h>
#include <cuda_bf16.h>
#include <stdint.h>
#include <math.h>

// Problem constants
#define Nn    50000
#define Mpad  50048
#define Ee    800000
#define FEAT  512
#define HEADS 8
#define HID   64
#define C1    512
#define NC    64
#define ALPHA 0.2f

// ---------------- scratch -----------------------------------------------------
__device__ float g_Wh [(size_t)Nn * C1];
__device__ float g_Wh2[(size_t)Nn * NC];
__device__ float g_fd1[Nn * HEADS];
__device__ float g_fs1[Nn * HEADS];
__device__ float g_fd2[Nn];
__device__ float g_fs2[Nn];
__device__ float g_lg1[(size_t)Ee * HEADS]; // CSR-ordered raw logits
__device__ float g_lg2[Ee];                 // CSR-ordered raw logits
__device__ int   g_cnt[Nn];
__device__ int   g_off[Nn + 1];
__device__ int   g_cur[Nn];
__device__ int   g_pos [Ee];
__device__ int   g_cols[Ee];

// bf16 hi/lo operands
__device__ __align__(256) __nv_bfloat16 g_xhi[(size_t)Mpad * 512];
__device__ __align__(256) __nv_bfloat16 g_xlo[(size_t)Mpad * 512];
__device__ __align__(256) __nv_bfloat16 g_bhi[512 * 512];
__device__ __align__(256) __nv_bfloat16 g_blo[512 * 512];
__device__ __align__(256) __nv_bfloat16 g_h1hi[(size_t)Mpad * 512];  // pad rows stay 0
__device__ __align__(256) __nv_bfloat16 g_h1lo[(size_t)Mpad * 512];
__device__ __align__(256) __nv_bfloat16 g_b2hi[64 * 512];
__device__ __align__(256) __nv_bfloat16 g_b2lo[64 * 512];

// ---------------- PTX helpers --------------------------------------------------
__device__ __forceinline__ uint32_t smem_u32(const void* p) {
    uint32_t a;
    asm("{ .reg .u64 t; cvta.to.shared.u64 t, %1; cvt.u32.u64 %0, t; }" : "=r"(a) : "l"(p));
    return a;
}
__device__ __forceinline__ void cpa16(uint32_t dst, const void* src) {
    asm volatile("cp.async.cg.shared.global [%0], [%1], 16;" :: "r"(dst), "l"(src));
}
__device__ __forceinline__ void cpa_commit() {
    asm volatile("cp.async.commit_group;" ::: "memory");
}
template <int N> __device__ __forceinline__ void cpa_wait() {
    asm volatile("cp.async.wait_group %0;" :: "n"(N) : "memory");
}
__device__ __forceinline__ void ldm4(uint32_t* r, uint32_t addr) {
    asm volatile("ldmatrix.sync.aligned.m8n8.x4.shared.b16 {%0,%1,%2,%3}, [%4];"
                 : "=r"(r[0]), "=r"(r[1]), "=r"(r[2]), "=r"(r[3]) : "r"(addr));
}
__device__ __forceinline__ void mma16816(float* c, const uint32_t* a,
                                         uint32_t b0, uint32_t b1) {
    asm volatile(
        "mma.sync.aligned.m16n8k16.row.col.f32.bf16.bf16.f32 "
        "{%0,%1,%2,%3}, {%4,%5,%6,%7}, {%8,%9}, {%0,%1,%2,%3};"
        : "+f"(c[0]), "+f"(c[1]), "+f"(c[2]), "+f"(c[3])
        : "r"(a[0]), "r"(a[1]), "r"(a[2]), "r"(a[3]), "r"(b0), "r"(b1));
}

// ---------------- conversion kernels --------------------------------------------
__global__ void k_cvt_x(const float* __restrict__ x) {
    long long i4 = (long long)blockIdx.x * blockDim.x + threadIdx.x;
    if (i4 >= (long long)Mpad * 128) return;
    long long row = i4 >> 7;
    float4 v = make_float4(0.f, 0.f, 0.f, 0.f);
    if (row < Nn) v = ((const float4*)x)[i4];
    __nv_bfloat16 h0 = __float2bfloat16_rn(v.x);
    __nv_bfloat16 h1 = __float2bfloat16_rn(v.y);
    __nv_bfloat16 h2 = __float2bfloat16_rn(v.z);
    __nv_bfloat16 h3 = __float2bfloat16_rn(v.w);
    __nv_bfloat16 l0 = __float2bfloat16_rn(v.x - __bfloat162float(h0));
    __nv_bfloat16 l1 = __float2bfloat16_rn(v.y - __bfloat162float(h1));
    __nv_bfloat16 l2 = __float2bfloat16_rn(v.z - __bfloat162float(h2));
    __nv_bfloat16 l3 = __float2bfloat16_rn(v.w - __bfloat162float(h3));
    __nv_bfloat16* ph = g_xhi + i4 * 4;
    __nv_bfloat16* pl = g_xlo + i4 * 4;
    ph[0] = h0; ph[1] = h1; ph[2] = h2; ph[3] = h3;
    pl[0] = l0; pl[1] = l1; pl[2] = l2; pl[3] = l3;
}

__global__ void k_cvt_w(const float* __restrict__ W) {
    int idx = blockIdx.x * blockDim.x + threadIdx.x;
    if (idx >= 512 * 512) return;
    int n = idx >> 9, k = idx & 511;
    float v = W[(size_t)(n >> 6) * (512 * 64) + (size_t)k * 64 + (n & 63)];
    __nv_bfloat16 h = __float2bfloat16_rn(v);
    __nv_bfloat16 l = __float2bfloat16_rn(v - __bfloat162float(h));
    g_bhi[idx] = h;
    g_blo[idx] = l;
}

__global__ void k_cvt_w2(const float* __restrict__ W_out) {
    int idx = blockIdx.x * blockDim.x + threadIdx.x;
    if (idx >= 64 * 512) return;
    int n = idx >> 9, k = idx & 511;
    float v = W_out[(size_t)k * 64 + n];
    __nv_bfloat16 h = __float2bfloat16_rn(v);
    __nv_bfloat16 l = __float2bfloat16_rn(v - __bfloat162float(h));
    g_b2hi[idx] = h;
    g_b2lo[idx] = l;
}

// ---------------- HMMA GEMM1 (+f1 epilogue), 2 CTAs/SM ---------------------------
#define A_HI 0
#define A_LO 10240
#define B_HI 20480
#define B_LO 30720
#define STAGE 40960
#define SMEM_GEMM_TOTAL (2 * STAGE)

__device__ __forceinline__ void load_stage(uint32_t s, int t, int m0, int n0, int kc) {
    int k0 = kc * 32;
#pragma unroll
    for (int i = 0; i < 2; i++) {
        int idx = t + i * 256;
        int r = idx >> 2;
        int c = idx & 3;
        uint32_t d = s + (uint32_t)(r * 80 + c * 16);
        size_t sa = (size_t)(m0 + r) * 512 + k0 + c * 8;
        size_t sbg = (size_t)(n0 + r) * 512 + k0 + c * 8;
        cpa16(d + A_HI, g_xhi + sa);
        cpa16(d + A_LO, g_xlo + sa);
        cpa16(d + B_HI, g_bhi + sbg);
        cpa16(d + B_LO, g_blo + sbg);
    }
    cpa_commit();
}

__global__ void __launch_bounds__(256, 2) k_gemm1_mma(const float* __restrict__ a_vec) {
    extern __shared__ char smem[];
    __shared__ float s_ad[2][64], s_as[2][64];
    uint32_t sb = smem_u32(smem);
    const int t = threadIdx.x;
    const int lane = t & 31, w = t >> 5;
    const int wm = w & 3, wn = w >> 2;
    const int m0 = blockIdx.x * 128, n0 = blockIdx.y * 128;

    if (t < 128) {
        int hh = t >> 6, j = t & 63;
        int gh = blockIdx.y * 2 + hh;
        s_ad[hh][j] = a_vec[gh * 128 + j];
        s_as[hh][j] = a_vec[gh * 128 + 64 + j];
    }

    float acc[2][8][4];
#pragma unroll
    for (int mf = 0; mf < 2; mf++)
#pragma unroll
        for (int nf = 0; nf < 8; nf++)
#pragma unroll
            for (int q = 0; q < 4; q++) acc[mf][nf][q] = 0.f;

    load_stage(sb, t, m0, n0, 0);

    const int a_row = wm * 32 + (lane & 15);
    const int a_colb = (lane >> 4) * 8;
    const int b_row = wn * 64 + ((lane >> 4) & 1) * 8 + (lane & 7);
    const int b_colb = ((lane >> 3) & 1) * 8;

    for (int kc = 0; kc < 16; kc++) {
        uint32_t s = sb + (uint32_t)(kc & 1) * STAGE;
        if (kc + 1 < 16) load_stage(sb + (uint32_t)((kc + 1) & 1) * STAGE, t, m0, n0, kc + 1);
        if (kc + 1 < 16) { cpa_wait<1>(); } else { cpa_wait<0>(); }
        __syncthreads();

#pragma unroll
        for (int ks = 0; ks < 2; ks++) {
            uint32_t ah[2][4], al[2][4];
#pragma unroll
            for (int mf = 0; mf < 2; mf++) {
                uint32_t ad = s + (uint32_t)((a_row + mf * 16) * 80 + (ks * 16 + a_colb) * 2);
                ldm4(ah[mf], ad + A_HI);
                ldm4(al[mf], ad + A_LO);
            }
            // B fragments loaded per-nb to keep live registers under 128
#pragma unroll
            for (int nb = 0; nb < 4; nb++) {
                uint32_t bh4[4], bl4[4];
                uint32_t bd = s + (uint32_t)((b_row + nb * 16) * 80 + (ks * 16 + b_colb) * 2);
                ldm4(bh4, bd + B_HI);
                ldm4(bl4, bd + B_LO);
#pragma unroll
                for (int mf = 0; mf < 2; mf++)
#pragma unroll
                    for (int half = 0; half < 2; half++) {
                        float* c = acc[mf][nb * 2 + half];
                        mma16816(c, ah[mf], bh4[half * 2], bh4[half * 2 + 1]);
                        mma16816(c, ah[mf], bl4[half * 2], bl4[half * 2 + 1]);
                        mma16816(c, al[mf], bh4[half * 2], bh4[half * 2 + 1]);
                    }
            }
        }
        __syncthreads();
    }

    // epilogue: store Wh + fused f1
    const int ghead = blockIdx.y * 2 + wn;
#pragma unroll
    for (int mf = 0; mf < 2; mf++) {
        int rbase = m0 + wm * 32 + mf * 16 + (lane >> 2);
#pragma unroll
        for (int nf = 0; nf < 8; nf++) {
            int cc = n0 + wn * 64 + nf * 8 + (lane & 3) * 2;
            float* c = acc[mf][nf];
            if (rbase < Nn)
                *(float2*)(g_Wh + (size_t)rbase * 512 + cc) = make_float2(c[0], c[1]);
            if (rbase + 8 < Nn)
                *(float2*)(g_Wh + (size_t)(rbase + 8) * 512 + cc) = make_float2(c[2], c[3]);
        }
#pragma unroll
        for (int half = 0; half < 2; half++) {
            float pd = 0.f, ps = 0.f;
#pragma unroll
            for (int nf = 0; nf < 8; nf++) {
                int j0 = nf * 8 + (lane & 3) * 2;
                float c0 = acc[mf][nf][half * 2 + 0];
                float c1 = acc[mf][nf][half * 2 + 1];
                pd += c0 * s_ad[wn][j0] + c1 * s_ad[wn][j0 + 1];
                ps += c0 * s_as[wn][j0] + c1 * s_as[wn][j0 + 1];
            }
            pd += __shfl_xor_sync(0xffffffffu, pd, 1);
            pd += __shfl_xor_sync(0xffffffffu, pd, 2);
            ps += __shfl_xor_sync(0xffffffffu, ps, 1);
            ps += __shfl_xor_sync(0xffffffffu, ps, 2);
            int r = rbase + half * 8;
            if ((lane & 3) == 0 && r < Nn) {
                g_fd1[r * 8 + ghead] = pd;
                g_fs1[r * 8 + ghead] = ps;
            }
        }
    }
}

// ---------------- HMMA GEMM2 (+f2 epilogue) -----------------------------------
#define A2_HI 0
#define A2_LO 10240
#define B2_HI 20480
#define B2_LO 25600
#define STAGE2 30720
#define SMEM_GEMM2_TOTAL (2 * STAGE2)

__device__ __forceinline__ void load_stage2(uint32_t s, int t, int m0, int kc) {
    int k0 = kc * 32;
#pragma unroll
    for (int i = 0; i < 2; i++) {
        int idx = t + i * 256;
        int r = idx >> 2;
        int c = idx & 3;
        uint32_t d = s + (uint32_t)(r * 80 + c * 16);
        size_t sa = (size_t)(m0 + r) * 512 + k0 + c * 8;
        cpa16(d + A2_HI, g_h1hi + sa);
        cpa16(d + A2_LO, g_h1lo + sa);
    }
    if (t < 256) {
        int r = t >> 2, c = t & 3;
        uint32_t d = s + (uint32_t)(r * 80 + c * 16);
        size_t sbg = (size_t)r * 512 + k0 + c * 8;
        cpa16(d + B2_HI, g_b2hi + sbg);
        cpa16(d + B2_LO, g_b2lo + sbg);
    }
    cpa_commit();
}

__global__ void __launch_bounds__(256, 2) k_gemm2_mma(const float* __restrict__ a_out) {
    extern __shared__ char smem[];
    __shared__ float s_a2d[64], s_a2s[64];
    __shared__ float s_pd[2][128], s_ps[2][128];
    uint32_t sb = smem_u32(smem);
    const int t = threadIdx.x;
    const int lane = t & 31, w = t >> 5;
    const int wm = w & 3, wn = w >> 2;
    const int m0 = blockIdx.x * 128;

    if (t < 64) {
        s_a2d[t] = a_out[t];
        s_a2s[t] = a_out[64 + t];
    }

    float acc[2][4][4];
#pragma unroll
    for (int mf = 0; mf < 2; mf++)
#pragma unroll
        for (int nf = 0; nf < 4; nf++)
#pragma unroll
            for (int q = 0; q < 4; q++) acc[mf][nf][q] = 0.f;

    load_stage2(sb, t, m0, 0);

    const int a_row = wm * 32 + (lane & 15);
    const int a_colb = (lane >> 4) * 8;
    const int b_row = wn * 32 + ((lane >> 4) & 1) * 8 + (lane & 7);
    const int b_colb = ((lane >> 3) & 1) * 8;

    for (int kc = 0; kc < 16; kc++) {
        uint32_t s = sb + (uint32_t)(kc & 1) * STAGE2;
        if (kc + 1 < 16) load_stage2(sb + (uint32_t)((kc + 1) & 1) * STAGE2, t, m0, kc + 1);
        if (kc + 1 < 16) { cpa_wait<1>(); } else { cpa_wait<0>(); }
        __syncthreads();

#pragma unroll
        for (int ks = 0; ks < 2; ks++) {
            uint32_t ah[2][4], al[2][4];
#pragma unroll
            for (int mf = 0; mf < 2; mf++) {
                uint32_t ad = s + (uint32_t)((a_row + mf * 16) * 80 + (ks * 16 + a_colb) * 2);
                ldm4(ah[mf], ad + A2_HI);
                ldm4(al[mf], ad + A2_LO);
            }
#pragma unroll
            for (int nb = 0; nb < 2; nb++) {
                uint32_t bh4[4], bl4[4];
                uint32_t bd = s + (uint32_t)((b_row + nb * 16) * 80 + (ks * 16 + b_colb) * 2);
                ldm4(bh4, bd + B2_HI);
                ldm4(bl4, bd + B2_LO);
#pragma unroll
                for (int mf = 0; mf < 2; mf++)
#pragma unroll
                    for (int half = 0; half < 2; half++) {
                        float* c = acc[mf][nb * 2 + half];
                        mma16816(c, ah[mf], bh4[half * 2], bh4[half * 2 + 1]);
                        mma16816(c, ah[mf], bl4[half * 2], bl4[half * 2 + 1]);
                        mma16816(c, al[mf], bh4[half * 2], bh4[half * 2 + 1]);
                    }
            }
        }
        __syncthreads();
    }

#pragma unroll
    for (int mf = 0; mf < 2; mf++) {
        int rbase = m0 + wm * 32 + mf * 16 + (lane >> 2);
#pragma unroll
        for (int nf = 0; nf < 4; nf++) {
            int cc = wn * 32 + nf * 8 + (lane & 3) * 2;
            float* c = acc[mf][nf];
            if (rbase < Nn)
                *(float2*)(g_Wh2 + (size_t)rbase * 64 + cc) = make_float2(c[0], c[1]);
            if (rbase + 8 < Nn)
                *(float2*)(g_Wh2 + (size_t)(rbase + 8) * 64 + cc) = make_float2(c[2], c[3]);
        }
#pragma unroll
        for (int half = 0; half < 2; half++) {
            float pd = 0.f, ps = 0.f;
#pragma unroll
            for (int nf = 0; nf < 4; nf++) {
                int j0 = wn * 32 + nf * 8 + (lane & 3) * 2;
                float c0 = acc[mf][nf][half * 2 + 0];
                float c1 = acc[mf][nf][half * 2 + 1];
                pd += c0 * s_a2d[j0] + c1 * s_a2d[j0 + 1];
                ps += c0 * s_a2s[j0] + c1 * s_a2s[j0 + 1];
            }
            pd += __shfl_xor_sync(0xffffffffu, pd, 1);
            pd += __shfl_xor_sync(0xffffffffu, pd, 2);
            ps += __shfl_xor_sync(0xffffffffu, ps, 1);
            ps += __shfl_xor_sync(0xffffffffu, ps, 2);
            int rl = wm * 32 + mf * 16 + (lane >> 2) + half * 8;
            if ((lane & 3) == 0) {
                s_pd[wn][rl] = pd;
                s_ps[wn][rl] = ps;
            }
        }
    }
    __syncthreads();
    if (t < 128) {
        int r = m0 + t;
        if (r < Nn) {
            g_fd2[r] = s_pd[0][t] + s_pd[1][t];
            g_fs2[r] = s_ps[0][t] + s_ps[1][t];
        }
    }
}

// ---------------- CSR build ------------------------------------------------
__global__ void k_zero_cnt() {
    int i = blockIdx.x * blockDim.x + threadIdx.x;
    if (i < Nn) g_cnt[i] = 0;
}

__global__ void k_hist(const int* __restrict__ row) {
    int e = blockIdx.x * blockDim.x + threadIdx.x;
    if (e < Ee) atomicAdd(&g_cnt[row[e]], 1);
}

__global__ void k_scan() {   // 1024 threads, shfl-based
    __shared__ int s_w[32];
    __shared__ int s_base, s_next;
    int t = threadIdx.x, lane = t & 31, wid = t >> 5;
    if (t == 0) s_base = 0;
    __syncthreads();
    for (int start = 0; start < Nn; start += 1024) {
        int i = start + t;
        int v = (i < Nn) ? g_cnt[i] : 0;
        int sc = v;
#pragma unroll
        for (int d = 1; d < 32; d <<= 1) {
            int u = __shfl_up_sync(0xffffffffu, sc, d);
            if (lane >= d) sc += u;
        }
        if (lane == 31) s_w[wid] = sc;
        __syncthreads();
        if (wid == 0) {
            int wsc = s_w[lane];
#pragma unroll
            for (int d = 1; d < 32; d <<= 1) {
                int u = __shfl_up_sync(0xffffffffu, wsc, d);
                if (lane >= d) wsc += u;
            }
            s_w[lane] = wsc;
            if (lane == 31) s_next = wsc;
        }
        __syncthreads();
        int base = s_base;
        int warpoff = (wid == 0) ? 0 : s_w[wid - 1];
        int ex = base + warpoff + sc - v;
        if (i < Nn) { g_off[i] = ex; g_cur[i] = ex; }
        __syncthreads();
        if (t == 0) s_base = base + s_next;
        __syncthreads();
    }
    if (t == 0) g_off[Nn] = s_base;
}

__global__ void k_scatter(const int* __restrict__ row, const int* __restrict__ col) {
    int e = blockIdx.x * blockDim.x + threadIdx.x;
    if (e < Ee) {
        int r = row[e];
        int p = atomicAdd(&g_cur[r], 1);
        g_pos[e]  = p;
        g_cols[p] = col[e];
    }
}

// ---------------- layer1: edge logits -> CSR slots --------------------------
__global__ void k_logits1(const int* __restrict__ row, const int* __restrict__ col) {
    int e = blockIdx.x * blockDim.x + threadIdx.x;
    if (e >= Ee) return;
    int r = row[e], c = col[e];
    float4 d0 = *(const float4*)(g_fd1 + r * 8);
    float4 d1 = *(const float4*)(g_fd1 + r * 8 + 4);
    float4 s0 = *(const float4*)(g_fs1 + c * 8);
    float4 s1 = *(const float4*)(g_fs1 + c * 8 + 4);
    float v[8] = {d0.x + s0.x, d0.y + s0.y, d0.z + s0.z, d0.w + s0.w,
                  d1.x + s1.x, d1.y + s1.y, d1.z + s1.z, d1.w + s1.w};
#pragma unroll
    for (int h = 0; h < 8; h++) v[h] = v[h] > 0.f ? v[h] : ALPHA * v[h];
    size_t p = (size_t)g_pos[e] * 8;
    *(float4*)(g_lg1 + p)     = make_float4(v[0], v[1], v[2], v[3]);
    *(float4*)(g_lg1 + p + 4) = make_float4(v[4], v[5], v[6], v[7]);
}

// ---------------- layer1: fused softmax stats + aggregation + ELU ------------
__global__ void __launch_bounds__(256) k_agg1() {
    int i = blockIdx.x;
    int t = threadIdx.x;
    int o = g_off[i], oe = g_off[i + 1];
    __shared__ float s_red[32][8];
    __shared__ float s_mx[8], s_iv[8];
    __shared__ float s_att[32][8];
    __shared__ int   s_col[32];
    int j = t >> 3, h = t & 7;

    float mx = -3.4e38f;
    for (int p = o + j; p < oe; p += 32)
        mx = fmaxf(mx, g_lg1[(size_t)p * 8 + h]);
    s_red[j][h] = mx;
    __syncthreads();
#pragma unroll
    for (int s = 16; s > 0; s >>= 1) {
        if (j < s) s_red[j][h] = fmaxf(s_red[j][h], s_red[j + s][h]);
        __syncthreads();
    }
    float mxh = s_red[0][h];
    __syncthreads();
    float sm = 0.f;
    for (int p = o + j; p < oe; p += 32)
        sm += __expf(g_lg1[(size_t)p * 8 + h] - mxh);
    s_red[j][h] = sm;
    __syncthreads();
#pragma unroll
    for (int s = 16; s > 0; s >>= 1) {
        if (j < s) s_red[j][h] += s_red[j + s][h];
        __syncthreads();
    }
    if (j == 0) {
        s_mx[h] = (oe > o) ? mxh : 0.f;
        s_iv[h] = (oe > o) ? 1.f / fmaxf(s_red[0][h], 1e-16f) : 0.f;
    }
    __syncthreads();

    int ha = t >> 6;
    int hb = ha + 4;
    float acc0 = 0.f, acc1 = 0.f;
    for (int base = o; base < oe; base += 32) {
        int cnt = min(32, oe - base);
        __syncthreads();
        if (j < cnt)
            s_att[j][h] = __expf(g_lg1[(size_t)(base + j) * 8 + h] - s_mx[h]) * s_iv[h];
        if (t < cnt) s_col[t] = g_cols[base + t];
        __syncthreads();
        for (int q = 0; q < cnt; q++) {
            int c = s_col[q];
            const float* whc = g_Wh + (size_t)c * 512;
            acc0 = fmaf(s_att[q][ha], whc[t], acc0);
            acc1 = fmaf(s_att[q][hb], whc[t + 256], acc1);
        }
    }
    float v0 = acc0 > 0.f ? acc0 : (__expf(acc0) - 1.f);
    float v1 = acc1 > 0.f ? acc1 : (__expf(acc1) - 1.f);
    size_t basew = (size_t)i * 512;
    __nv_bfloat16 h0 = __float2bfloat16_rn(v0);
    __nv_bfloat16 h1 = __float2bfloat16_rn(v1);
    g_h1hi[basew + t]       = h0;
    g_h1hi[basew + t + 256] = h1;
    g_h1lo[basew + t]       = __float2bfloat16_rn(v0 - __bfloat162float(h0));
    g_h1lo[basew + t + 256] = __float2bfloat16_rn(v1 - __bfloat162float(h1));
}

// ---------------- layer2: edge logits ---------------------------------------
__global__ void k_logits2(const int* __restrict__ row, const int* __restrict__ col) {
    int e = blockIdx.x * blockDim.x + threadIdx.x;
    if (e >= Ee) return;
    float v = g_fd2[row[e]] + g_fs2[col[e]];
    g_lg2[g_pos[e]] = v > 0.f ? v : ALPHA * v;
}

// ---------------- layer2: fused stats + aggregation --------------------------
__global__ void __launch_bounds__(64) k_agg2(float* __restrict__ out) {
    int i = blockIdx.x;
    int t = threadIdx.x;  // 64
    int o = g_off[i], oe = g_off[i + 1];
    __shared__ float s_r[64];
    __shared__ float s_att[64];
    __shared__ int   s_col[64];

    float mx = -3.4e38f;
    for (int p = o + t; p < oe; p += 64) mx = fmaxf(mx, g_lg2[p]);
    s_r[t] = mx;
    __syncthreads();
#pragma unroll
    for (int s = 32; s > 0; s >>= 1) {
        if (t < s) s_r[t] = fmaxf(s_r[t], s_r[t + s]);
        __syncthreads();
    }
    float M = s_r[0];
    __syncthreads();
    float sm = 0.f;
    for (int p = o + t; p < oe; p += 64) sm += __expf(g_lg2[p] - M);
    s_r[t] = sm;
    __syncthreads();
#pragma unroll
    for (int s = 32; s > 0; s >>= 1) {
        if (t < s) s_r[t] += s_r[t + s];
        __syncthreads();
    }
    float iv = (oe > o) ? 1.f / fmaxf(s_r[0], 1e-16f) : 0.f;
    __syncthreads();

    float acc = 0.f;
    for (int base = o; base < oe; base += 64) {
        int cnt = min(64, oe - base);
        __syncthreads();
        if (t < cnt) {
            s_att[t] = __expf(g_lg2[base + t] - M) * iv;
            s_col[t] = g_cols[base + t];
        }
        __syncthreads();
        for (int q = 0; q < cnt; q++)
            acc = fmaf(s_att[q], g_Wh2[(size_t)s_col[q] * 64 + t], acc);
    }
    out[(size_t)i * 64 + t] = acc;
}

// ---------------- launch -----------------------------------------------------
extern "C" void kernel_launch(void* const* d_in, const int* in_sizes, int n_in,
                              void* d_out, int out_size) {
    const float* x     = (const float*)d_in[0];
    const int*   row   = (const int*)  d_in[1];
    const int*   col   = (const int*)  d_in[2];
    const float* W     = (const float*)d_in[3];
    const float* a     = (const float*)d_in[4];
    const float* W_out = (const float*)d_in[5];
    const float* a_out = (const float*)d_in[6];
    float* out = (float*)d_out;

    const int EB = (Ee + 255) / 256;

    cudaFuncSetAttribute(k_gemm1_mma, cudaFuncAttributeMaxDynamicSharedMemorySize,
                         SMEM_GEMM_TOTAL);
    cudaFuncSetAttribute(k_gemm2_mma, cudaFuncAttributeMaxDynamicSharedMemorySize,
                         SMEM_GEMM2_TOTAL);

    k_cvt_x<<<(int)(((long long)Mpad * 128 + 255) / 256), 256>>>(x);       // 0
    k_cvt_w<<<(512 * 512 + 255) / 256, 256>>>(W);                          // 1
    k_cvt_w2<<<(64 * 512 + 255) / 256, 256>>>(W_out);                      // 2
    k_gemm1_mma<<<dim3(Mpad / 128, 4), 256, SMEM_GEMM_TOTAL>>>(a);         // 3 <- profiled
    k_zero_cnt<<<(Nn + 255) / 256, 256>>>();                               // 4
    k_hist<<<EB, 256>>>(row);                                              // 5
    k_scan<<<1, 1024>>>();                                                 // 6
    k_scatter<<<EB, 256>>>(row, col);                                      // 7
    k_logits1<<<EB, 256>>>(row, col);                                      // 8
    k_agg1<<<Nn, 256>>>();                                                 // 9
    k_gemm2_mma<<<Mpad / 128, 256, SMEM_GEMM2_TOTAL>>>(a_out);             // 10
    k_logits2<<<EB, 256>>>(row, col);                                      // 11
    k_agg2<<<Nn, 64>>>(out);                                               // 12
}

// round 11
// speedup vs baseline: 1.0944x; 1.0469x over previous
#include <cuda_runtime.h>
#include <cuda_bf16.h>
#include <cuda_fp16.h>
#include <stdint.h>
#include <math.h>

// Problem constants
#define Nn    50000
#define Mpad  50048
#define Ee    800000
#define FEAT  512
#define HEADS 8
#define HID   64
#define C1    512
#define NC    64
#define ALPHA 0.2f

// ---------------- scratch -----------------------------------------------------
__device__ float g_Wh2[(size_t)Nn * NC];
__device__ float g_fd1[Nn * HEADS];
__device__ float g_fs1[Nn * HEADS];
__device__ float g_fd2[Nn];
__device__ float g_fs2[Nn];
__device__ float g_lg1[(size_t)Ee * HEADS]; // CSR-ordered raw logits
__device__ float g_lg2[Ee];                 // CSR-ordered raw logits
__device__ int   g_cnt[Nn];
__device__ int   g_off[Nn + 1];
__device__ int   g_cur[Nn];
__device__ int   g_pos [Ee];
__device__ int   g_cols[Ee];

// bf16 operands / fp16 intermediate
__device__ __align__(256) __nv_bfloat16 g_xhi[(size_t)Mpad * 512];
__device__ __align__(256) __nv_bfloat16 g_xlo[(size_t)Mpad * 512];
__device__ __align__(256) __nv_bfloat16 g_bhi[512 * 512];
__device__ __align__(256) __nv_bfloat16 g_blo[512 * 512];
__device__ __align__(256) __half        g_Whb[(size_t)Nn * 512];     // layer1 Wh in fp16
__device__ __align__(256) __nv_bfloat16 g_h1hi[(size_t)Mpad * 512];  // pad rows stay 0
__device__ __align__(256) __nv_bfloat16 g_h1lo[(size_t)Mpad * 512];
__device__ __align__(256) __nv_bfloat16 g_b2hi[64 * 512];
__device__ __align__(256) __nv_bfloat16 g_b2lo[64 * 512];

// ---------------- PTX helpers --------------------------------------------------
__device__ __forceinline__ uint32_t smem_u32(const void* p) {
    uint32_t a;
    asm("{ .reg .u64 t; cvta.to.shared.u64 t, %1; cvt.u32.u64 %0, t; }" : "=r"(a) : "l"(p));
    return a;
}
__device__ __forceinline__ void cpa16(uint32_t dst, const void* src) {
    asm volatile("cp.async.cg.shared.global [%0], [%1], 16;" :: "r"(dst), "l"(src));
}
__device__ __forceinline__ void cpa_commit() {
    asm volatile("cp.async.commit_group;" ::: "memory");
}
template <int N> __device__ __forceinline__ void cpa_wait() {
    asm volatile("cp.async.wait_group %0;" :: "n"(N) : "memory");
}
__device__ __forceinline__ void ldm4(uint32_t* r, uint32_t addr) {
    asm volatile("ldmatrix.sync.aligned.m8n8.x4.shared.b16 {%0,%1,%2,%3}, [%4];"
                 : "=r"(r[0]), "=r"(r[1]), "=r"(r[2]), "=r"(r[3]) : "r"(addr));
}
__device__ __forceinline__ void mma16816(float* c, const uint32_t* a,
                                         uint32_t b0, uint32_t b1) {
    asm volatile(
        "mma.sync.aligned.m16n8k16.row.col.f32.bf16.bf16.f32 "
        "{%0,%1,%2,%3}, {%4,%5,%6,%7}, {%8,%9}, {%0,%1,%2,%3};"
        : "+f"(c[0]), "+f"(c[1]), "+f"(c[2]), "+f"(c[3])
        : "r"(a[0]), "r"(a[1]), "r"(a[2]), "r"(a[3]), "r"(b0), "r"(b1));
}

// ---------------- conversion / init kernels -------------------------------------
__global__ void k_cvt_x(const float* __restrict__ x) {
    long long i4 = (long long)blockIdx.x * blockDim.x + threadIdx.x;
    if (i4 >= (long long)Mpad * 128) return;
    long long row = i4 >> 7;
    float4 v = make_float4(0.f, 0.f, 0.f, 0.f);
    if (row < Nn) v = ((const float4*)x)[i4];
    __nv_bfloat16 h0 = __float2bfloat16_rn(v.x);
    __nv_bfloat16 h1 = __float2bfloat16_rn(v.y);
    __nv_bfloat16 h2 = __float2bfloat16_rn(v.z);
    __nv_bfloat16 h3 = __float2bfloat16_rn(v.w);
    __nv_bfloat16 l0 = __float2bfloat16_rn(v.x - __bfloat162float(h0));
    __nv_bfloat16 l1 = __float2bfloat16_rn(v.y - __bfloat162float(h1));
    __nv_bfloat16 l2 = __float2bfloat16_rn(v.z - __bfloat162float(h2));
    __nv_bfloat16 l3 = __float2bfloat16_rn(v.w - __bfloat162float(h3));
    __nv_bfloat16* ph = g_xhi + i4 * 4;
    __nv_bfloat16* pl = g_xlo + i4 * 4;
    ph[0] = h0; ph[1] = h1; ph[2] = h2; ph[3] = h3;
    pl[0] = l0; pl[1] = l1; pl[2] = l2; pl[3] = l3;
}

// merged: W1 convert + W_out convert + zero g_cnt
__global__ void k_init_misc(const float* __restrict__ W,
                            const float* __restrict__ W_out) {
    int idx = blockIdx.x * blockDim.x + threadIdx.x;
    if (idx < 512 * 512) {
        int n = idx >> 9, k = idx & 511;
        float v = W[(size_t)(n >> 6) * (512 * 64) + (size_t)k * 64 + (n & 63)];
        __nv_bfloat16 h = __float2bfloat16_rn(v);
        g_bhi[idx] = h;
        g_blo[idx] = __float2bfloat16_rn(v - __bfloat162float(h));
    }
    if (idx < 64 * 512) {
        int n = idx >> 9, k = idx & 511;
        float v = W_out[(size_t)k * 64 + n];
        __nv_bfloat16 h = __float2bfloat16_rn(v);
        g_b2hi[idx] = h;
        g_b2lo[idx] = __float2bfloat16_rn(v - __bfloat162float(h));
    }
    if (idx < Nn) g_cnt[idx] = 0;
}

// ---------------- HMMA GEMM1 (+f1 epilogue), 2 CTAs/SM ---------------------------
#define A_HI 0
#define A_LO 10240
#define B_HI 20480
#define B_LO 30720
#define STAGE 40960
#define SMEM_GEMM_TOTAL (2 * STAGE)

__device__ __forceinline__ void load_stage(uint32_t s, int t, int m0, int n0, int kc) {
    int k0 = kc * 32;
#pragma unroll
    for (int i = 0; i < 2; i++) {
        int idx = t + i * 256;
        int r = idx >> 2;
        int c = idx & 3;
        uint32_t d = s + (uint32_t)(r * 80 + c * 16);
        size_t sa = (size_t)(m0 + r) * 512 + k0 + c * 8;
        size_t sbg = (size_t)(n0 + r) * 512 + k0 + c * 8;
        cpa16(d + A_HI, g_xhi + sa);
        cpa16(d + A_LO, g_xlo + sa);
        cpa16(d + B_HI, g_bhi + sbg);
        cpa16(d + B_LO, g_blo + sbg);
    }
    cpa_commit();
}

__global__ void __launch_bounds__(256, 2) k_gemm1_mma(const float* __restrict__ a_vec) {
    extern __shared__ char smem[];
    __shared__ float s_ad[2][64], s_as[2][64];
    uint32_t sb = smem_u32(smem);
    const int t = threadIdx.x;
    const int lane = t & 31, w = t >> 5;
    const int wm = w & 3, wn = w >> 2;
    const int m0 = blockIdx.x * 128, n0 = blockIdx.y * 128;

    if (t < 128) {
        int hh = t >> 6, j = t & 63;
        int gh = blockIdx.y * 2 + hh;
        s_ad[hh][j] = a_vec[gh * 128 + j];
        s_as[hh][j] = a_vec[gh * 128 + 64 + j];
    }

    float acc[2][8][4];
#pragma unroll
    for (int mf = 0; mf < 2; mf++)
#pragma unroll
        for (int nf = 0; nf < 8; nf++)
#pragma unroll
            for (int q = 0; q < 4; q++) acc[mf][nf][q] = 0.f;

    load_stage(sb, t, m0, n0, 0);

    const int a_row = wm * 32 + (lane & 15);
    const int a_colb = (lane >> 4) * 8;
    const int b_row = wn * 64 + ((lane >> 4) & 1) * 8 + (lane & 7);
    const int b_colb = ((lane >> 3) & 1) * 8;

    for (int kc = 0; kc < 16; kc++) {
        uint32_t s = sb + (uint32_t)(kc & 1) * STAGE;
        if (kc + 1 < 16) load_stage(sb + (uint32_t)((kc + 1) & 1) * STAGE, t, m0, n0, kc + 1);
        if (kc + 1 < 16) { cpa_wait<1>(); } else { cpa_wait<0>(); }
        __syncthreads();

#pragma unroll
        for (int ks = 0; ks < 2; ks++) {
            uint32_t ah[2][4], al[2][4];
#pragma unroll
            for (int mf = 0; mf < 2; mf++) {
                uint32_t ad = s + (uint32_t)((a_row + mf * 16) * 80 + (ks * 16 + a_colb) * 2);
                ldm4(ah[mf], ad + A_HI);
                ldm4(al[mf], ad + A_LO);
            }
#pragma unroll
            for (int nb = 0; nb < 4; nb++) {
                uint32_t bh4[4], bl4[4];
                uint32_t bd = s + (uint32_t)((b_row + nb * 16) * 80 + (ks * 16 + b_colb) * 2);
                ldm4(bh4, bd + B_HI);
                ldm4(bl4, bd + B_LO);
#pragma unroll
                for (int mf = 0; mf < 2; mf++)
#pragma unroll
                    for (int half = 0; half < 2; half++) {
                        float* c = acc[mf][nb * 2 + half];
                        mma16816(c, ah[mf], bh4[half * 2], bh4[half * 2 + 1]);
                        mma16816(c, ah[mf], bl4[half * 2], bl4[half * 2 + 1]);
                        mma16816(c, al[mf], bh4[half * 2], bh4[half * 2 + 1]);
                    }
            }
        }
        __syncthreads();
    }

    // epilogue: store Wh (fp16) + fused f1 from fp32 accs
    const int ghead = blockIdx.y * 2 + wn;
#pragma unroll
    for (int mf = 0; mf < 2; mf++) {
        int rbase = m0 + wm * 32 + mf * 16 + (lane >> 2);
#pragma unroll
        for (int nf = 0; nf < 8; nf++) {
            int cc = n0 + wn * 64 + nf * 8 + (lane & 3) * 2;
            float* c = acc[mf][nf];
            if (rbase < Nn) {
                __half2 p;
                p.x = __float2half_rn(c[0]);
                p.y = __float2half_rn(c[1]);
                *(__half2*)(g_Whb + (size_t)rbase * 512 + cc) = p;
            }
            if (rbase + 8 < Nn) {
                __half2 p;
                p.x = __float2half_rn(c[2]);
                p.y = __float2half_rn(c[3]);
                *(__half2*)(g_Whb + (size_t)(rbase + 8) * 512 + cc) = p;
            }
        }
#pragma unroll
        for (int half = 0; half < 2; half++) {
            float pd = 0.f, ps = 0.f;
#pragma unroll
            for (int nf = 0; nf < 8; nf++) {
                int j0 = nf * 8 + (lane & 3) * 2;
                float c0 = acc[mf][nf][half * 2 + 0];
                float c1 = acc[mf][nf][half * 2 + 1];
                pd += c0 * s_ad[wn][j0] + c1 * s_ad[wn][j0 + 1];
                ps += c0 * s_as[wn][j0] + c1 * s_as[wn][j0 + 1];
            }
            pd += __shfl_xor_sync(0xffffffffu, pd, 1);
            pd += __shfl_xor_sync(0xffffffffu, pd, 2);
            ps += __shfl_xor_sync(0xffffffffu, ps, 1);
            ps += __shfl_xor_sync(0xffffffffu, ps, 2);
            int r = rbase + half * 8;
            if ((lane & 3) == 0 && r < Nn) {
                g_fd1[r * 8 + ghead] = pd;
                g_fs1[r * 8 + ghead] = ps;
            }
        }
    }
}

// ---------------- HMMA GEMM2 (+f2 epilogue) -----------------------------------
#define A2_HI 0
#define A2_LO 10240
#define B2_HI 20480
#define B2_LO 25600
#define STAGE2 30720
#define SMEM_GEMM2_TOTAL (2 * STAGE2)

__device__ __forceinline__ void load_stage2(uint32_t s, int t, int m0, int kc) {
    int k0 = kc * 32;
#pragma unroll
    for (int i = 0; i < 2; i++) {
        int idx = t + i * 256;
        int r = idx >> 2;
        int c = idx & 3;
        uint32_t d = s + (uint32_t)(r * 80 + c * 16);
        size_t sa = (size_t)(m0 + r) * 512 + k0 + c * 8;
        cpa16(d + A2_HI, g_h1hi + sa);
        cpa16(d + A2_LO, g_h1lo + sa);
    }
    if (t < 256) {
        int r = t >> 2, c = t & 3;
        uint32_t d = s + (uint32_t)(r * 80 + c * 16);
        size_t sbg = (size_t)r * 512 + k0 + c * 8;
        cpa16(d + B2_HI, g_b2hi + sbg);
        cpa16(d + B2_LO, g_b2lo + sbg);
    }
    cpa_commit();
}

__global__ void __launch_bounds__(256, 2) k_gemm2_mma(const float* __restrict__ a_out) {
    extern __shared__ char smem[];
    __shared__ float s_a2d[64], s_a2s[64];
    __shared__ float s_pd[2][128], s_ps[2][128];
    uint32_t sb = smem_u32(smem);
    const int t = threadIdx.x;
    const int lane = t & 31, w = t >> 5;
    const int wm = w & 3, wn = w >> 2;
    const int m0 = blockIdx.x * 128;

    if (t < 64) {
        s_a2d[t] = a_out[t];
        s_a2s[t] = a_out[64 + t];
    }

    float acc[2][4][4];
#pragma unroll
    for (int mf = 0; mf < 2; mf++)
#pragma unroll
        for (int nf = 0; nf < 4; nf++)
#pragma unroll
            for (int q = 0; q < 4; q++) acc[mf][nf][q] = 0.f;

    load_stage2(sb, t, m0, 0);

    const int a_row = wm * 32 + (lane & 15);
    const int a_colb = (lane >> 4) * 8;
    const int b_row = wn * 32 + ((lane >> 4) & 1) * 8 + (lane & 7);
    const int b_colb = ((lane >> 3) & 1) * 8;

    for (int kc = 0; kc < 16; kc++) {
        uint32_t s = sb + (uint32_t)(kc & 1) * STAGE2;
        if (kc + 1 < 16) load_stage2(sb + (uint32_t)((kc + 1) & 1) * STAGE2, t, m0, kc + 1);
        if (kc + 1 < 16) { cpa_wait<1>(); } else { cpa_wait<0>(); }
        __syncthreads();

#pragma unroll
        for (int ks = 0; ks < 2; ks++) {
            uint32_t ah[2][4], al[2][4];
#pragma unroll
            for (int mf = 0; mf < 2; mf++) {
                uint32_t ad = s + (uint32_t)((a_row + mf * 16) * 80 + (ks * 16 + a_colb) * 2);
                ldm4(ah[mf], ad + A2_HI);
                ldm4(al[mf], ad + A2_LO);
            }
#pragma unroll
            for (int nb = 0; nb < 2; nb++) {
                uint32_t bh4[4], bl4[4];
                uint32_t bd = s + (uint32_t)((b_row + nb * 16) * 80 + (ks * 16 + b_colb) * 2);
                ldm4(bh4, bd + B2_HI);
                ldm4(bl4, bd + B2_LO);
#pragma unroll
                for (int mf = 0; mf < 2; mf++)
#pragma unroll
                    for (int half = 0; half < 2; half++) {
                        float* c = acc[mf][nb * 2 + half];
                        mma16816(c, ah[mf], bh4[half * 2], bh4[half * 2 + 1]);
                        mma16816(c, ah[mf], bl4[half * 2], bl4[half * 2 + 1]);
                        mma16816(c, al[mf], bh4[half * 2], bh4[half * 2 + 1]);
                    }
            }
        }
        __syncthreads();
    }

#pragma unroll
    for (int mf = 0; mf < 2; mf++) {
        int rbase = m0 + wm * 32 + mf * 16 + (lane >> 2);
#pragma unroll
        for (int nf = 0; nf < 4; nf++) {
            int cc = wn * 32 + nf * 8 + (lane & 3) * 2;
            float* c = acc[mf][nf];
            if (rbase < Nn)
                *(float2*)(g_Wh2 + (size_t)rbase * 64 + cc) = make_float2(c[0], c[1]);
            if (rbase + 8 < Nn)
                *(float2*)(g_Wh2 + (size_t)(rbase + 8) * 64 + cc) = make_float2(c[2], c[3]);
        }
#pragma unroll
        for (int half = 0; half < 2; half++) {
            float pd = 0.f, ps = 0.f;
#pragma unroll
            for (int nf = 0; nf < 4; nf++) {
                int j0 = wn * 32 + nf * 8 + (lane & 3) * 2;
                float c0 = acc[mf][nf][half * 2 + 0];
                float c1 = acc[mf][nf][half * 2 + 1];
                pd += c0 * s_a2d[j0] + c1 * s_a2d[j0 + 1];
                ps += c0 * s_a2s[j0] + c1 * s_a2s[j0 + 1];
            }
            pd += __shfl_xor_sync(0xffffffffu, pd, 1);
            pd += __shfl_xor_sync(0xffffffffu, pd, 2);
            ps += __shfl_xor_sync(0xffffffffu, ps, 1);
            ps += __shfl_xor_sync(0xffffffffu, ps, 2);
            int rl = wm * 32 + mf * 16 + (lane >> 2) + half * 8;
            if ((lane & 3) == 0) {
                s_pd[wn][rl] = pd;
                s_ps[wn][rl] = ps;
            }
        }
    }
    __syncthreads();
    if (t < 128) {
        int r = m0 + t;
        if (r < Nn) {
            g_fd2[r] = s_pd[0][t] + s_pd[1][t];
            g_fs2[r] = s_ps[0][t] + s_ps[1][t];
        }
    }
}

// ---------------- CSR build ------------------------------------------------
__global__ void k_hist(const int* __restrict__ row) {
    int e = blockIdx.x * blockDim.x + threadIdx.x;
    if (e < Ee) atomicAdd(&g_cnt[row[e]], 1);
}

__global__ void k_scan() {   // 1024 threads, shfl-based
    __shared__ int s_w[32];
    __shared__ int s_base, s_next;
    int t = threadIdx.x, lane = t & 31, wid = t >> 5;
    if (t == 0) s_base = 0;
    __syncthreads();
    for (int start = 0; start < Nn; start += 1024) {
        int i = start + t;
        int v = (i < Nn) ? g_cnt[i] : 0;
        int sc = v;
#pragma unroll
        for (int d = 1; d < 32; d <<= 1) {
            int u = __shfl_up_sync(0xffffffffu, sc, d);
            if (lane >= d) sc += u;
        }
        if (lane == 31) s_w[wid] = sc;
        __syncthreads();
        if (wid == 0) {
            int wsc = s_w[lane];
#pragma unroll
            for (int d = 1; d < 32; d <<= 1) {
                int u = __shfl_up_sync(0xffffffffu, wsc, d);
                if (lane >= d) wsc += u;
            }
            s_w[lane] = wsc;
            if (lane == 31) s_next = wsc;
        }
        __syncthreads();
        int base = s_base;
        int warpoff = (wid == 0) ? 0 : s_w[wid - 1];
        int ex = base + warpoff + sc - v;
        if (i < Nn) { g_off[i] = ex; g_cur[i] = ex; }
        __syncthreads();
        if (t == 0) s_base = base + s_next;
        __syncthreads();
    }
    if (t == 0) g_off[Nn] = s_base;
}

__global__ void k_scatter(const int* __restrict__ row, const int* __restrict__ col) {
    int e = blockIdx.x * blockDim.x + threadIdx.x;
    if (e < Ee) {
        int r = row[e];
        int p = atomicAdd(&g_cur[r], 1);
        g_pos[e]  = p;
        g_cols[p] = col[e];
    }
}

// ---------------- layer1: edge logits -> CSR slots --------------------------
__global__ void k_logits1(const int* __restrict__ row, const int* __restrict__ col) {
    int e = blockIdx.x * blockDim.x + threadIdx.x;
    if (e >= Ee) return;
    int r = row[e], c = col[e];
    float4 d0 = *(const float4*)(g_fd1 + r * 8);
    float4 d1 = *(const float4*)(g_fd1 + r * 8 + 4);
    float4 s0 = *(const float4*)(g_fs1 + c * 8);
    float4 s1 = *(const float4*)(g_fs1 + c * 8 + 4);
    float v[8] = {d0.x + s0.x, d0.y + s0.y, d0.z + s0.z, d0.w + s0.w,
                  d1.x + s1.x, d1.y + s1.y, d1.z + s1.z, d1.w + s1.w};
#pragma unroll
    for (int h = 0; h < 8; h++) v[h] = v[h] > 0.f ? v[h] : ALPHA * v[h];
    size_t p = (size_t)g_pos[e] * 8;
    *(float4*)(g_lg1 + p)     = make_float4(v[0], v[1], v[2], v[3]);
    *(float4*)(g_lg1 + p + 4) = make_float4(v[4], v[5], v[6], v[7]);
}

// ---------------- layer1: fused softmax stats + fp16 gather agg + ELU --------
__global__ void __launch_bounds__(256) k_agg1() {
    int i = blockIdx.x;
    int t = threadIdx.x;
    int o = g_off[i], oe = g_off[i + 1];
    __shared__ float s_red[32][8];
    __shared__ float s_mx[8], s_iv[8];
    __shared__ float s_att[32][8];
    __shared__ int   s_col[32];
    int j = t >> 3, h = t & 7;

    float mx = -3.4e38f;
    for (int p = o + j; p < oe; p += 32)
        mx = fmaxf(mx, g_lg1[(size_t)p * 8 + h]);
    s_red[j][h] = mx;
    __syncthreads();
#pragma unroll
    for (int s = 16; s > 0; s >>= 1) {
        if (j < s) s_red[j][h] = fmaxf(s_red[j][h], s_red[j + s][h]);
        __syncthreads();
    }
    float mxh = s_red[0][h];
    __syncthreads();
    float sm = 0.f;
    for (int p = o + j; p < oe; p += 32)
        sm += __expf(g_lg1[(size_t)p * 8 + h] - mxh);
    s_red[j][h] = sm;
    __syncthreads();
#pragma unroll
    for (int s = 16; s > 0; s >>= 1) {
        if (j < s) s_red[j][h] += s_red[j + s][h];
        __syncthreads();
    }
    if (j == 0) {
        s_mx[h] = (oe > o) ? mxh : 0.f;
        s_iv[h] = (oe > o) ? 1.f / fmaxf(s_red[0][h], 1e-16f) : 0.f;
    }
    __syncthreads();

    // each thread handles dims (2t, 2t+1); head = t>>5
    int ha = t >> 5;
    float acc0 = 0.f, acc1 = 0.f;
    for (int base = o; base < oe; base += 32) {
        int cnt = min(32, oe - base);
        __syncthreads();
        if (j < cnt)
            s_att[j][h] = __expf(g_lg1[(size_t)(base + j) * 8 + h] - s_mx[h]) * s_iv[h];
        if (t < cnt) s_col[t] = g_cols[base + t];
        __syncthreads();
        for (int q = 0; q < cnt; q++) {
            int c = s_col[q];
            const __half2* whc = (const __half2*)(g_Whb + (size_t)c * 512);
            float2 v = __half22float2(whc[t]);
            float wv = s_att[q][ha];
            acc0 = fmaf(wv, v.x, acc0);
            acc1 = fmaf(wv, v.y, acc1);
        }
    }
    float v0 = acc0 > 0.f ? acc0 : (__expf(acc0) - 1.f);
    float v1 = acc1 > 0.f ? acc1 : (__expf(acc1) - 1.f);
    size_t basew = (size_t)i * 512 + 2 * t;
    __nv_bfloat162 hp, lp;
    hp.x = __float2bfloat16_rn(v0);
    hp.y = __float2bfloat16_rn(v1);
    lp.x = __float2bfloat16_rn(v0 - __bfloat162float(hp.x));
    lp.y = __float2bfloat16_rn(v1 - __bfloat162float(hp.y));
    *(__nv_bfloat162*)(g_h1hi + basew) = hp;
    *(__nv_bfloat162*)(g_h1lo + basew) = lp;
}

// ---------------- layer2: edge logits ---------------------------------------
__global__ void k_logits2(const int* __restrict__ row, const int* __restrict__ col) {
    int e = blockIdx.x * blockDim.x + threadIdx.x;
    if (e >= Ee) return;
    float v = g_fd2[row[e]] + g_fs2[col[e]];
    g_lg2[g_pos[e]] = v > 0.f ? v : ALPHA * v;
}

// ---------------- layer2: fused stats + aggregation --------------------------
__global__ void __launch_bounds__(64) k_agg2(float* __restrict__ out) {
    int i = blockIdx.x;
    int t = threadIdx.x;  // 64
    int o = g_off[i], oe = g_off[i + 1];
    __shared__ float s_r[64];
    __shared__ float s_att[64];
    __shared__ int   s_col[64];

    float mx = -3.4e38f;
    for (int p = o + t; p < oe; p += 64) mx = fmaxf(mx, g_lg2[p]);
    s_r[t] = mx;
    __syncthreads();
#pragma unroll
    for (int s = 32; s > 0; s >>= 1) {
        if (t < s) s_r[t] = fmaxf(s_r[t], s_r[t + s]);
        __syncthreads();
    }
    float M = s_r[0];
    __syncthreads();
    float sm = 0.f;
    for (int p = o + t; p < oe; p += 64) sm += __expf(g_lg2[p] - M);
    s_r[t] = sm;
    __syncthreads();
#pragma unroll
    for (int s = 32; s > 0; s >>= 1) {
        if (t < s) s_r[t] += s_r[t + s];
        __syncthreads();
    }
    float iv = (oe > o) ? 1.f / fmaxf(s_r[0], 1e-16f) : 0.f;
    __syncthreads();

    float acc = 0.f;
    for (int base = o; base < oe; base += 64) {
        int cnt = min(64, oe - base);
        __syncthreads();
        if (t < cnt) {
            s_att[t] = __expf(g_lg2[base + t] - M) * iv;
            s_col[t] = g_cols[base + t];
        }
        __syncthreads();
        for (int q = 0; q < cnt; q++)
            acc = fmaf(s_att[q], g_Wh2[(size_t)s_col[q] * 64 + t], acc);
    }
    out[(size_t)i * 64 + t] = acc;
}

// ---------------- launch -----------------------------------------------------
extern "C" void kernel_launch(void* const* d_in, const int* in_sizes, int n_in,
                              void* d_out, int out_size) {
    const float* x     = (const float*)d_in[0];
    const int*   row   = (const int*)  d_in[1];
    const int*   col   = (const int*)  d_in[2];
    const float* W     = (const float*)d_in[3];
    const float* a     = (const float*)d_in[4];
    const float* W_out = (const float*)d_in[5];
    const float* a_out = (const float*)d_in[6];
    float* out = (float*)d_out;

    const int EB = (Ee + 255) / 256;

    cudaFuncSetAttribute(k_gemm1_mma, cudaFuncAttributeMaxDynamicSharedMemorySize,
                         SMEM_GEMM_TOTAL);
    cudaFuncSetAttribute(k_gemm2_mma, cudaFuncAttributeMaxDynamicSharedMemorySize,
                         SMEM_GEMM2_TOTAL);

    k_cvt_x<<<(int)(((long long)Mpad * 128 + 255) / 256), 256>>>(x);       // 0
    k_init_misc<<<(512 * 512 + 255) / 256, 256>>>(W, W_out);               // 1
    k_hist<<<EB, 256>>>(row);                                              // 2
    k_gemm1_mma<<<dim3(Mpad / 128, 4), 256, SMEM_GEMM_TOTAL>>>(a);         // 3 <- profiled
    k_scan<<<1, 1024>>>();                                                 // 4
    k_scatter<<<EB, 256>>>(row, col);                                      // 5
    k_logits1<<<EB, 256>>>(row, col);                                      // 6
    k_agg1<<<Nn, 256>>>();                                                 // 7
    k_gemm2_mma<<<Mpad / 128, 256, SMEM_GEMM2_TOTAL>>>(a_out);             // 8
    k_logits2<<<EB, 256>>>(row, col);                                      // 9
    k_agg2<<<Nn, 64>>>(out);                                               // 10
}

// round 12
// speedup vs baseline: 1.4247x; 1.3018x over previous
#include <cuda_runtime.h>
#include <cuda_bf16.h>
#include <cuda_fp16.h>
#include <stdint.h>
#include <math.h>

// Problem constants
#define Nn    50000
#define Mpad  50048
#define Ee    800000
#define FEAT  512
#define HEADS 8
#define HID   64
#define C1    512
#define NC    64
#define ALPHA 0.2f

// ---------------- scratch -----------------------------------------------------
__device__ float g_Wh2[(size_t)Nn * NC];
__device__ float g_fd1[Nn * HEADS];
__device__ float g_fs1[Nn * HEADS];
__device__ float g_fd2[Nn];
__device__ float g_fs2[Nn];
__device__ float g_lg1[(size_t)Ee * HEADS]; // CSR-ordered raw logits
__device__ float g_lg2[Ee];                 // CSR-ordered raw logits
__device__ int   g_cnt[Nn];
__device__ int   g_off[Nn + 1];
__device__ int   g_cur[Nn];
__device__ int   g_pos [Ee];
__device__ int   g_cols[Ee];

// operands / intermediates
__device__ __align__(256) __half        g_xh [(size_t)Mpad * 512];   // x in fp16
__device__ __align__(256) __half        g_bh [512 * 512];            // W1t in fp16
__device__ __align__(256) __half        g_Whb[(size_t)Nn * 512];     // layer1 Wh in fp16
__device__ __align__(256) __nv_bfloat16 g_h1hi[(size_t)Mpad * 512];  // pad rows stay 0
__device__ __align__(256) __nv_bfloat16 g_h1lo[(size_t)Mpad * 512];
__device__ __align__(256) __nv_bfloat16 g_b2hi[64 * 512];
__device__ __align__(256) __nv_bfloat16 g_b2lo[64 * 512];

// ---------------- PTX helpers --------------------------------------------------
__device__ __forceinline__ uint32_t smem_u32(const void* p) {
    uint32_t a;
    asm("{ .reg .u64 t; cvta.to.shared.u64 t, %1; cvt.u32.u64 %0, t; }" : "=r"(a) : "l"(p));
    return a;
}
__device__ __forceinline__ void cpa16(uint32_t dst, const void* src) {
    asm volatile("cp.async.cg.shared.global [%0], [%1], 16;" :: "r"(dst), "l"(src));
}
__device__ __forceinline__ void cpa_commit() {
    asm volatile("cp.async.commit_group;" ::: "memory");
}
template <int N> __device__ __forceinline__ void cpa_wait() {
    asm volatile("cp.async.wait_group %0;" :: "n"(N) : "memory");
}
__device__ __forceinline__ void ldm4(uint32_t* r, uint32_t addr) {
    asm volatile("ldmatrix.sync.aligned.m8n8.x4.shared.b16 {%0,%1,%2,%3}, [%4];"
                 : "=r"(r[0]), "=r"(r[1]), "=r"(r[2]), "=r"(r[3]) : "r"(addr));
}
// bf16 MMA (layer 2)
__device__ __forceinline__ void mma16816(float* c, const uint32_t* a,
                                         uint32_t b0, uint32_t b1) {
    asm volatile(
        "mma.sync.aligned.m16n8k16.row.col.f32.bf16.bf16.f32 "
        "{%0,%1,%2,%3}, {%4,%5,%6,%7}, {%8,%9}, {%0,%1,%2,%3};"
        : "+f"(c[0]), "+f"(c[1]), "+f"(c[2]), "+f"(c[3])
        : "r"(a[0]), "r"(a[1]), "r"(a[2]), "r"(a[3]), "r"(b0), "r"(b1));
}
// fp16 MMA (layer 1)
__device__ __forceinline__ void mma16816h(float* c, const uint32_t* a,
                                          uint32_t b0, uint32_t b1) {
    asm volatile(
        "mma.sync.aligned.m16n8k16.row.col.f32.f16.f16.f32 "
        "{%0,%1,%2,%3}, {%4,%5,%6,%7}, {%8,%9}, {%0,%1,%2,%3};"
        : "+f"(c[0]), "+f"(c[1]), "+f"(c[2]), "+f"(c[3])
        : "r"(a[0]), "r"(a[1]), "r"(a[2]), "r"(a[3]), "r"(b0), "r"(b1));
}

// ---------------- conversion / init kernels -------------------------------------
__global__ void k_cvt_x(const float* __restrict__ x) {
    long long i4 = (long long)blockIdx.x * blockDim.x + threadIdx.x;
    if (i4 >= (long long)Mpad * 128) return;
    long long row = i4 >> 7;
    float4 v = make_float4(0.f, 0.f, 0.f, 0.f);
    if (row < Nn) v = ((const float4*)x)[i4];
    __half2 p0, p1;
    p0.x = __float2half_rn(v.x); p0.y = __float2half_rn(v.y);
    p1.x = __float2half_rn(v.z); p1.y = __float2half_rn(v.w);
    *(__half2*)(g_xh + i4 * 4)     = p0;
    *(__half2*)(g_xh + i4 * 4 + 2) = p1;
}

// merged: W1 convert (fp16) + W_out convert (bf16 hi/lo) + zero g_cnt
__global__ void k_init_misc(const float* __restrict__ W,
                            const float* __restrict__ W_out) {
    int idx = blockIdx.x * blockDim.x + threadIdx.x;
    if (idx < 512 * 512) {
        int n = idx >> 9, k = idx & 511;
        float v = W[(size_t)(n >> 6) * (512 * 64) + (size_t)k * 64 + (n & 63)];
        g_bh[idx] = __float2half_rn(v);
    }
    if (idx < 64 * 512) {
        int n = idx >> 9, k = idx & 511;
        float v = W_out[(size_t)k * 64 + n];
        __nv_bfloat16 h = __float2bfloat16_rn(v);
        g_b2hi[idx] = h;
        g_b2lo[idx] = __float2bfloat16_rn(v - __bfloat162float(h));
    }
    if (idx < Nn) g_cnt[idx] = 0;
}

// ---------------- fp16 HMMA GEMM1 (+f1 epilogue), 2 CTAs/SM ----------------------
#define A_OFF 0
#define B_OFF 10240
#define STAGE 20480
#define SMEM_GEMM_TOTAL (2 * STAGE)

__device__ __forceinline__ void load_stage(uint32_t s, int t, int m0, int n0, int kc) {
    int k0 = kc * 32;
#pragma unroll
    for (int i = 0; i < 2; i++) {
        int idx = t + i * 256;
        int r = idx >> 2;
        int c = idx & 3;
        uint32_t d = s + (uint32_t)(r * 80 + c * 16);
        size_t sa = (size_t)(m0 + r) * 512 + k0 + c * 8;
        size_t sbg = (size_t)(n0 + r) * 512 + k0 + c * 8;
        cpa16(d + A_OFF, g_xh + sa);
        cpa16(d + B_OFF, g_bh + sbg);
    }
    cpa_commit();
}

__global__ void __launch_bounds__(256, 2) k_gemm1_mma(const float* __restrict__ a_vec) {
    extern __shared__ char smem[];
    __shared__ float s_ad[2][64], s_as[2][64];
    uint32_t sb = smem_u32(smem);
    const int t = threadIdx.x;
    const int lane = t & 31, w = t >> 5;
    const int wm = w & 3, wn = w >> 2;
    const int m0 = blockIdx.x * 128, n0 = blockIdx.y * 128;

    if (t < 128) {
        int hh = t >> 6, j = t & 63;
        int gh = blockIdx.y * 2 + hh;
        s_ad[hh][j] = a_vec[gh * 128 + j];
        s_as[hh][j] = a_vec[gh * 128 + 64 + j];
    }

    float acc[2][8][4];
#pragma unroll
    for (int mf = 0; mf < 2; mf++)
#pragma unroll
        for (int nf = 0; nf < 8; nf++)
#pragma unroll
            for (int q = 0; q < 4; q++) acc[mf][nf][q] = 0.f;

    load_stage(sb, t, m0, n0, 0);

    const int a_row = wm * 32 + (lane & 15);
    const int a_colb = (lane >> 4) * 8;
    const int b_row = wn * 64 + ((lane >> 4) & 1) * 8 + (lane & 7);
    const int b_colb = ((lane >> 3) & 1) * 8;

    for (int kc = 0; kc < 16; kc++) {
        uint32_t s = sb + (uint32_t)(kc & 1) * STAGE;
        if (kc + 1 < 16) load_stage(sb + (uint32_t)((kc + 1) & 1) * STAGE, t, m0, n0, kc + 1);
        if (kc + 1 < 16) { cpa_wait<1>(); } else { cpa_wait<0>(); }
        __syncthreads();

#pragma unroll
        for (int ks = 0; ks < 2; ks++) {
            uint32_t ah[2][4];
#pragma unroll
            for (int mf = 0; mf < 2; mf++) {
                uint32_t ad = s + A_OFF +
                    (uint32_t)((a_row + mf * 16) * 80 + (ks * 16 + a_colb) * 2);
                ldm4(ah[mf], ad);
            }
#pragma unroll
            for (int nb = 0; nb < 4; nb++) {
                uint32_t bh4[4];
                uint32_t bd = s + B_OFF +
                    (uint32_t)((b_row + nb * 16) * 80 + (ks * 16 + b_colb) * 2);
                ldm4(bh4, bd);
#pragma unroll
                for (int mf = 0; mf < 2; mf++)
#pragma unroll
                    for (int half = 0; half < 2; half++) {
                        float* c = acc[mf][nb * 2 + half];
                        mma16816h(c, ah[mf], bh4[half * 2], bh4[half * 2 + 1]);
                    }
            }
        }
        __syncthreads();
    }

    // epilogue: store Wh (fp16) + fused f1 from fp32 accs
    const int ghead = blockIdx.y * 2 + wn;
#pragma unroll
    for (int mf = 0; mf < 2; mf++) {
        int rbase = m0 + wm * 32 + mf * 16 + (lane >> 2);
#pragma unroll
        for (int nf = 0; nf < 8; nf++) {
            int cc = n0 + wn * 64 + nf * 8 + (lane & 3) * 2;
            float* c = acc[mf][nf];
            if (rbase < Nn) {
                __half2 p;
                p.x = __float2half_rn(c[0]);
                p.y = __float2half_rn(c[1]);
                *(__half2*)(g_Whb + (size_t)rbase * 512 + cc) = p;
            }
            if (rbase + 8 < Nn) {
                __half2 p;
                p.x = __float2half_rn(c[2]);
                p.y = __float2half_rn(c[3]);
                *(__half2*)(g_Whb + (size_t)(rbase + 8) * 512 + cc) = p;
            }
        }
#pragma unroll
        for (int half = 0; half < 2; half++) {
            float pd = 0.f, ps = 0.f;
#pragma unroll
            for (int nf = 0; nf < 8; nf++) {
                int j0 = nf * 8 + (lane & 3) * 2;
                float c0 = acc[mf][nf][half * 2 + 0];
                float c1 = acc[mf][nf][half * 2 + 1];
                pd += c0 * s_ad[wn][j0] + c1 * s_ad[wn][j0 + 1];
                ps += c0 * s_as[wn][j0] + c1 * s_as[wn][j0 + 1];
            }
            pd += __shfl_xor_sync(0xffffffffu, pd, 1);
            pd += __shfl_xor_sync(0xffffffffu, pd, 2);
            ps += __shfl_xor_sync(0xffffffffu, ps, 1);
            ps += __shfl_xor_sync(0xffffffffu, ps, 2);
            int r = rbase + half * 8;
            if ((lane & 3) == 0 && r < Nn) {
                g_fd1[r * 8 + ghead] = pd;
                g_fs1[r * 8 + ghead] = ps;
            }
        }
    }
}

// ---------------- HMMA GEMM2 (+f2 epilogue), bf16 hi/lo --------------------------
#define A2_HI 0
#define A2_LO 10240
#define B2_HI 20480
#define B2_LO 25600
#define STAGE2 30720
#define SMEM_GEMM2_TOTAL (2 * STAGE2)

__device__ __forceinline__ void load_stage2(uint32_t s, int t, int m0, int kc) {
    int k0 = kc * 32;
#pragma unroll
    for (int i = 0; i < 2; i++) {
        int idx = t + i * 256;
        int r = idx >> 2;
        int c = idx & 3;
        uint32_t d = s + (uint32_t)(r * 80 + c * 16);
        size_t sa = (size_t)(m0 + r) * 512 + k0 + c * 8;
        cpa16(d + A2_HI, g_h1hi + sa);
        cpa16(d + A2_LO, g_h1lo + sa);
    }
    if (t < 256) {
        int r = t >> 2, c = t & 3;
        uint32_t d = s + (uint32_t)(r * 80 + c * 16);
        size_t sbg = (size_t)r * 512 + k0 + c * 8;
        cpa16(d + B2_HI, g_b2hi + sbg);
        cpa16(d + B2_LO, g_b2lo + sbg);
    }
    cpa_commit();
}

__global__ void __launch_bounds__(256, 2) k_gemm2_mma(const float* __restrict__ a_out) {
    extern __shared__ char smem[];
    __shared__ float s_a2d[64], s_a2s[64];
    __shared__ float s_pd[2][128], s_ps[2][128];
    uint32_t sb = smem_u32(smem);
    const int t = threadIdx.x;
    const int lane = t & 31, w = t >> 5;
    const int wm = w & 3, wn = w >> 2;
    const int m0 = blockIdx.x * 128;

    if (t < 64) {
        s_a2d[t] = a_out[t];
        s_a2s[t] = a_out[64 + t];
    }

    float acc[2][4][4];
#pragma unroll
    for (int mf = 0; mf < 2; mf++)
#pragma unroll
        for (int nf = 0; nf < 4; nf++)
#pragma unroll
            for (int q = 0; q < 4; q++) acc[mf][nf][q] = 0.f;

    load_stage2(sb, t, m0, 0);

    const int a_row = wm * 32 + (lane & 15);
    const int a_colb = (lane >> 4) * 8;
    const int b_row = wn * 32 + ((lane >> 4) & 1) * 8 + (lane & 7);
    const int b_colb = ((lane >> 3) & 1) * 8;

    for (int kc = 0; kc < 16; kc++) {
        uint32_t s = sb + (uint32_t)(kc & 1) * STAGE2;
        if (kc + 1 < 16) load_stage2(sb + (uint32_t)((kc + 1) & 1) * STAGE2, t, m0, kc + 1);
        if (kc + 1 < 16) { cpa_wait<1>(); } else { cpa_wait<0>(); }
        __syncthreads();

#pragma unroll
        for (int ks = 0; ks < 2; ks++) {
            uint32_t ah[2][4], al[2][4];
#pragma unroll
            for (int mf = 0; mf < 2; mf++) {
                uint32_t ad = s + (uint32_t)((a_row + mf * 16) * 80 + (ks * 16 + a_colb) * 2);
                ldm4(ah[mf], ad + A2_HI);
                ldm4(al[mf], ad + A2_LO);
            }
#pragma unroll
            for (int nb = 0; nb < 2; nb++) {
                uint32_t bh4[4], bl4[4];
                uint32_t bd = s + (uint32_t)((b_row + nb * 16) * 80 + (ks * 16 + b_colb) * 2);
                ldm4(bh4, bd + B2_HI);
                ldm4(bl4, bd + B2_LO);
#pragma unroll
                for (int mf = 0; mf < 2; mf++)
#pragma unroll
                    for (int half = 0; half < 2; half++) {
                        float* c = acc[mf][nb * 2 + half];
                        mma16816(c, ah[mf], bh4[half * 2], bh4[half * 2 + 1]);
                        mma16816(c, ah[mf], bl4[half * 2], bl4[half * 2 + 1]);
                        mma16816(c, al[mf], bh4[half * 2], bh4[half * 2 + 1]);
                    }
            }
        }
        __syncthreads();
    }

#pragma unroll
    for (int mf = 0; mf < 2; mf++) {
        int rbase = m0 + wm * 32 + mf * 16 + (lane >> 2);
#pragma unroll
        for (int nf = 0; nf < 4; nf++) {
            int cc = wn * 32 + nf * 8 + (lane & 3) * 2;
            float* c = acc[mf][nf];
            if (rbase < Nn)
                *(float2*)(g_Wh2 + (size_t)rbase * 64 + cc) = make_float2(c[0], c[1]);
            if (rbase + 8 < Nn)
                *(float2*)(g_Wh2 + (size_t)(rbase + 8) * 64 + cc) = make_float2(c[2], c[3]);
        }
#pragma unroll
        for (int half = 0; half < 2; half++) {
            float pd = 0.f, ps = 0.f;
#pragma unroll
            for (int nf = 0; nf < 4; nf++) {
                int j0 = wn * 32 + nf * 8 + (lane & 3) * 2;
                float c0 = acc[mf][nf][half * 2 + 0];
                float c1 = acc[mf][nf][half * 2 + 1];
                pd += c0 * s_a2d[j0] + c1 * s_a2d[j0 + 1];
                ps += c0 * s_a2s[j0] + c1 * s_a2s[j0 + 1];
            }
            pd += __shfl_xor_sync(0xffffffffu, pd, 1);
            pd += __shfl_xor_sync(0xffffffffu, pd, 2);
            ps += __shfl_xor_sync(0xffffffffu, ps, 1);
            ps += __shfl_xor_sync(0xffffffffu, ps, 2);
            int rl = wm * 32 + mf * 16 + (lane >> 2) + half * 8;
            if ((lane & 3) == 0) {
                s_pd[wn][rl] = pd;
                s_ps[wn][rl] = ps;
            }
        }
    }
    __syncthreads();
    if (t < 128) {
        int r = m0 + t;
        if (r < Nn) {
            g_fd2[r] = s_pd[0][t] + s_pd[1][t];
            g_fs2[r] = s_ps[0][t] + s_ps[1][t];
        }
    }
}

// ---------------- CSR build ------------------------------------------------
__global__ void k_hist(const int* __restrict__ row) {
    int e = blockIdx.x * blockDim.x + threadIdx.x;
    if (e < Ee) atomicAdd(&g_cnt[row[e]], 1);
}

__global__ void k_scan() {   // 1024 threads, shfl-based
    __shared__ int s_w[32];
    __shared__ int s_base, s_next;
    int t = threadIdx.x, lane = t & 31, wid = t >> 5;
    if (t == 0) s_base = 0;
    __syncthreads();
    for (int start = 0; start < Nn; start += 1024) {
        int i = start + t;
        int v = (i < Nn) ? g_cnt[i] : 0;
        int sc = v;
#pragma unroll
        for (int d = 1; d < 32; d <<= 1) {
            int u = __shfl_up_sync(0xffffffffu, sc, d);
            if (lane >= d) sc += u;
        }
        if (lane == 31) s_w[wid] = sc;
        __syncthreads();
        if (wid == 0) {
            int wsc = s_w[lane];
#pragma unroll
            for (int d = 1; d < 32; d <<= 1) {
                int u = __shfl_up_sync(0xffffffffu, wsc, d);
                if (lane >= d) wsc += u;
            }
            s_w[lane] = wsc;
            if (lane == 31) s_next = wsc;
        }
        __syncthreads();
        int base = s_base;
        int warpoff = (wid == 0) ? 0 : s_w[wid - 1];
        int ex = base + warpoff + sc - v;
        if (i < Nn) { g_off[i] = ex; g_cur[i] = ex; }
        __syncthreads();
        if (t == 0) s_base = base + s_next;
        __syncthreads();
    }
    if (t == 0) g_off[Nn] = s_base;
}

__global__ void k_scatter(const int* __restrict__ row, const int* __restrict__ col) {
    int e = blockIdx.x * blockDim.x + threadIdx.x;
    if (e < Ee) {
        int r = row[e];
        int p = atomicAdd(&g_cur[r], 1);
        g_pos[e]  = p;
        g_cols[p] = col[e];
    }
}

// ---------------- layer1: edge logits -> CSR slots --------------------------
__global__ void k_logits1(const int* __restrict__ row, const int* __restrict__ col) {
    int e = blockIdx.x * blockDim.x + threadIdx.x;
    if (e >= Ee) return;
    int r = row[e], c = col[e];
    float4 d0 = *(const float4*)(g_fd1 + r * 8);
    float4 d1 = *(const float4*)(g_fd1 + r * 8 + 4);
    float4 s0 = *(const float4*)(g_fs1 + c * 8);
    float4 s1 = *(const float4*)(g_fs1 + c * 8 + 4);
    float v[8] = {d0.x + s0.x, d0.y + s0.y, d0.z + s0.z, d0.w + s0.w,
                  d1.x + s1.x, d1.y + s1.y, d1.z + s1.z, d1.w + s1.w};
#pragma unroll
    for (int h = 0; h < 8; h++) v[h] = v[h] > 0.f ? v[h] : ALPHA * v[h];
    size_t p = (size_t)g_pos[e] * 8;
    *(float4*)(g_lg1 + p)     = make_float4(v[0], v[1], v[2], v[3]);
    *(float4*)(g_lg1 + p + 4) = make_float4(v[4], v[5], v[6], v[7]);
}

// ---------------- layer1: fused softmax stats + fp16 gather agg + ELU --------
__global__ void __launch_bounds__(256) k_agg1() {
    int i = blockIdx.x;
    int t = threadIdx.x;
    int o = g_off[i], oe = g_off[i + 1];
    __shared__ float s_red[32][8];
    __shared__ float s_mx[8], s_iv[8];
    __shared__ float s_att[32][8];
    __shared__ int   s_col[32];
    int j = t >> 3, h = t & 7;

    float mx = -3.4e38f;
    for (int p = o + j; p < oe; p += 32)
        mx = fmaxf(mx, g_lg1[(size_t)p * 8 + h]);
    s_red[j][h] = mx;
    __syncthreads();
#pragma unroll
    for (int s = 16; s > 0; s >>= 1) {
        if (j < s) s_red[j][h] = fmaxf(s_red[j][h], s_red[j + s][h]);
        __syncthreads();
    }
    float mxh = s_red[0][h];
    __syncthreads();
    float sm = 0.f;
    for (int p = o + j; p < oe; p += 32)
        sm += __expf(g_lg1[(size_t)p * 8 + h] - mxh);
    s_red[j][h] = sm;
    __syncthreads();
#pragma unroll
    for (int s = 16; s > 0; s >>= 1) {
        if (j < s) s_red[j][h] += s_red[j + s][h];
        __syncthreads();
    }
    if (j == 0) {
        s_mx[h] = (oe > o) ? mxh : 0.f;
        s_iv[h] = (oe > o) ? 1.f / fmaxf(s_red[0][h], 1e-16f) : 0.f;
    }
    __syncthreads();

    // each thread handles dims (2t, 2t+1); head = t>>5
    int ha = t >> 5;
    float acc0 = 0.f, acc1 = 0.f;
    for (int base = o; base < oe; base += 32) {
        int cnt = min(32, oe - base);
        __syncthreads();
        if (j < cnt)
            s_att[j][h] = __expf(g_lg1[(size_t)(base + j) * 8 + h] - s_mx[h]) * s_iv[h];
        if (t < cnt) s_col[t] = g_cols[base + t];
        __syncthreads();
        for (int q = 0; q < cnt; q++) {
            int c = s_col[q];
            const __half2* whc = (const __half2*)(g_Whb + (size_t)c * 512);
            float2 v = __half22float2(whc[t]);
            float wv = s_att[q][ha];
            acc0 = fmaf(wv, v.x, acc0);
            acc1 = fmaf(wv, v.y, acc1);
        }
    }
    float v0 = acc0 > 0.f ? acc0 : (__expf(acc0) - 1.f);
    float v1 = acc1 > 0.f ? acc1 : (__expf(acc1) - 1.f);
    size_t basew = (size_t)i * 512 + 2 * t;
    __nv_bfloat162 hp, lp;
    hp.x = __float2bfloat16_rn(v0);
    hp.y = __float2bfloat16_rn(v1);
    lp.x = __float2bfloat16_rn(v0 - __bfloat162float(hp.x));
    lp.y = __float2bfloat16_rn(v1 - __bfloat162float(hp.y));
    *(__nv_bfloat162*)(g_h1hi + basew) = hp;
    *(__nv_bfloat162*)(g_h1lo + basew) = lp;
}

// ---------------- layer2: edge logits ---------------------------------------
__global__ void k_logits2(const int* __restrict__ row, const int* __restrict__ col) {
    int e = blockIdx.x * blockDim.x + threadIdx.x;
    if (e >= Ee) return;
    float v = g_fd2[row[e]] + g_fs2[col[e]];
    g_lg2[g_pos[e]] = v > 0.f ? v : ALPHA * v;
}

// ---------------- layer2: fused stats + aggregation --------------------------
__global__ void __launch_bounds__(64) k_agg2(float* __restrict__ out) {
    int i = blockIdx.x;
    int t = threadIdx.x;  // 64
    int o = g_off[i], oe = g_off[i + 1];
    __shared__ float s_r[64];
    __shared__ float s_att[64];
    __shared__ int   s_col[64];

    float mx = -3.4e38f;
    for (int p = o + t; p < oe; p += 64) mx = fmaxf(mx, g_lg2[p]);
    s_r[t] = mx;
    __syncthreads();
#pragma unroll
    for (int s = 32; s > 0; s >>= 1) {
        if (t < s) s_r[t] = fmaxf(s_r[t], s_r[t + s]);
        __syncthreads();
    }
    float M = s_r[0];
    __syncthreads();
    float sm = 0.f;
    for (int p = o + t; p < oe; p += 64) sm += __expf(g_lg2[p] - M);
    s_r[t] = sm;
    __syncthreads();
#pragma unroll
    for (int s = 32; s > 0; s >>= 1) {
        if (t < s) s_r[t] += s_r[t + s];
        __syncthreads();
    }
    float iv = (oe > o) ? 1.f / fmaxf(s_r[0], 1e-16f) : 0.f;
    __syncthreads();

    float acc = 0.f;
    for (int base = o; base < oe; base += 64) {
        int cnt = min(64, oe - base);
        __syncthreads();
        if (t < cnt) {
            s_att[t] = __expf(g_lg2[base + t] - M) * iv;
            s_col[t] = g_cols[base + t];
        }
        __syncthreads();
        for (int q = 0; q < cnt; q++)
            acc = fmaf(s_att[q], g_Wh2[(size_t)s_col[q] * 64 + t], acc);
    }
    out[(size_t)i * 64 + t] = acc;
}

// ---------------- launch -----------------------------------------------------
extern "C" void kernel_launch(void* const* d_in, const int* in_sizes, int n_in,
                              void* d_out, int out_size) {
    const float* x     = (const float*)d_in[0];
    const int*   row   = (const int*)  d_in[1];
    const int*   col   = (const int*)  d_in[2];
    const float* W     = (const float*)d_in[3];
    const float* a     = (const float*)d_in[4];
    const float* W_out = (const float*)d_in[5];
    const float* a_out = (const float*)d_in[6];
    float* out = (float*)d_out;

    const int EB = (Ee + 255) / 256;

    cudaFuncSetAttribute(k_gemm1_mma, cudaFuncAttributeMaxDynamicSharedMemorySize,
                         SMEM_GEMM_TOTAL);
    cudaFuncSetAttribute(k_gemm2_mma, cudaFuncAttributeMaxDynamicSharedMemorySize,
                         SMEM_GEMM2_TOTAL);

    k_cvt_x<<<(int)(((long long)Mpad * 128 + 255) / 256), 256>>>(x);       // 0
    k_init_misc<<<(512 * 512 + 255) / 256, 256>>>(W, W_out);               // 1
    k_hist<<<EB, 256>>>(row);                                              // 2
    k_gemm1_mma<<<dim3(Mpad / 128, 4), 256, SMEM_GEMM_TOTAL>>>(a);         // 3 <- profiled
    k_scan<<<1, 1024>>>();                                                 // 4
    k_scatter<<<EB, 256>>>(row, col);                                      // 5
    k_logits1<<<EB, 256>>>(row, col);                                      // 6
    k_agg1<<<Nn, 256>>>();                                                 // 7
    k_gemm2_mma<<<Mpad / 128, 256, SMEM_GEMM2_TOTAL>>>(a_out);             // 8
    k_logits2<<<EB, 256>>>(row, col);                                      // 9
    k_agg2<<<Nn, 64>>>(out);                                               // 10
}

// round 13
// speedup vs baseline: 1.4942x; 1.0488x over previous
#include <cuda_runtime.h>
#include <cuda_bf16.h>
#include <cuda_fp16.h>
#include <stdint.h>
#include <math.h>

// Problem constants
#define Nn    50000
#define Mpad  50048
#define Ee    800000
#define FEAT  512
#define HEADS 8
#define HID   64
#define C1    512
#define NC    64
#define ALPHA 0.2f

// ---------------- scratch -----------------------------------------------------
__device__ float g_Wh2[(size_t)Nn * NC];
__device__ float g_fd1[Nn * HEADS];
__device__ float g_fs1[Nn * HEADS];
__device__ float g_fd2[Nn];
__device__ float g_fs2[Nn];
__device__ float g_lg1[(size_t)Ee * HEADS]; // CSR-ordered raw logits
__device__ float g_lg2[Ee];                 // CSR-ordered raw logits
__device__ int   g_cnt[Nn];
__device__ int   g_off[Nn + 1];
__device__ int   g_cur[Nn];
__device__ int   g_pos [Ee];
__device__ int   g_cols[Ee];

// fp16 operands / intermediates
__device__ __align__(256) __half g_xh [(size_t)Mpad * 512];   // x in fp16
__device__ __align__(256) __half g_bh [512 * 512];            // W1t in fp16
__device__ __align__(256) __half g_Whb[(size_t)Nn * 512];     // layer1 Wh in fp16
__device__ __align__(256) __half g_h1 [(size_t)Mpad * 512];   // h1 fp16 (pad rows stay 0)
__device__ __align__(256) __half g_b2 [64 * 512];             // W_out_t in fp16

// ---------------- PTX helpers --------------------------------------------------
__device__ __forceinline__ uint32_t smem_u32(const void* p) {
    uint32_t a;
    asm("{ .reg .u64 t; cvta.to.shared.u64 t, %1; cvt.u32.u64 %0, t; }" : "=r"(a) : "l"(p));
    return a;
}
__device__ __forceinline__ void cpa16(uint32_t dst, const void* src) {
    asm volatile("cp.async.cg.shared.global [%0], [%1], 16;" :: "r"(dst), "l"(src));
}
__device__ __forceinline__ void cpa_commit() {
    asm volatile("cp.async.commit_group;" ::: "memory");
}
template <int N> __device__ __forceinline__ void cpa_wait() {
    asm volatile("cp.async.wait_group %0;" :: "n"(N) : "memory");
}
__device__ __forceinline__ void ldm4(uint32_t* r, uint32_t addr) {
    asm volatile("ldmatrix.sync.aligned.m8n8.x4.shared.b16 {%0,%1,%2,%3}, [%4];"
                 : "=r"(r[0]), "=r"(r[1]), "=r"(r[2]), "=r"(r[3]) : "r"(addr));
}
// fp16 MMA
__device__ __forceinline__ void mma16816h(float* c, const uint32_t* a,
                                          uint32_t b0, uint32_t b1) {
    asm volatile(
        "mma.sync.aligned.m16n8k16.row.col.f32.f16.f16.f32 "
        "{%0,%1,%2,%3}, {%4,%5,%6,%7}, {%8,%9}, {%0,%1,%2,%3};"
        : "+f"(c[0]), "+f"(c[1]), "+f"(c[2]), "+f"(c[3])
        : "r"(a[0]), "r"(a[1]), "r"(a[2]), "r"(a[3]), "r"(b0), "r"(b1));
}

// ---------------- conversion / init kernels -------------------------------------
__global__ void k_cvt_x(const float* __restrict__ x) {
    long long i4 = (long long)blockIdx.x * blockDim.x + threadIdx.x;
    if (i4 >= (long long)Mpad * 128) return;
    long long row = i4 >> 7;
    float4 v = make_float4(0.f, 0.f, 0.f, 0.f);
    if (row < Nn) v = ((const float4*)x)[i4];
    __half2 p0, p1;
    p0.x = __float2half_rn(v.x); p0.y = __float2half_rn(v.y);
    p1.x = __float2half_rn(v.z); p1.y = __float2half_rn(v.w);
    *(__half2*)(g_xh + i4 * 4)     = p0;
    *(__half2*)(g_xh + i4 * 4 + 2) = p1;
}

// merged: W1 convert + W_out convert (fp16) + zero g_cnt
__global__ void k_init_misc(const float* __restrict__ W,
                            const float* __restrict__ W_out) {
    int idx = blockIdx.x * blockDim.x + threadIdx.x;
    if (idx < 512 * 512) {
        int n = idx >> 9, k = idx & 511;
        float v = W[(size_t)(n >> 6) * (512 * 64) + (size_t)k * 64 + (n & 63)];
        g_bh[idx] = __float2half_rn(v);
    }
    if (idx < 64 * 512) {
        int n = idx >> 9, k = idx & 511;
        g_b2[idx] = __float2half_rn(W_out[(size_t)k * 64 + n]);
    }
    if (idx < Nn) g_cnt[idx] = 0;
}

// ---------------- fp16 HMMA GEMM1 (+f1 epilogue), 2 CTAs/SM ----------------------
#define A_OFF 0
#define B_OFF 10240
#define STAGE 20480
#define SMEM_GEMM_TOTAL (2 * STAGE)

__device__ __forceinline__ void load_stage(uint32_t s, int t, int m0, int n0, int kc) {
    int k0 = kc * 32;
#pragma unroll
    for (int i = 0; i < 2; i++) {
        int idx = t + i * 256;
        int r = idx >> 2;
        int c = idx & 3;
        uint32_t d = s + (uint32_t)(r * 80 + c * 16);
        size_t sa = (size_t)(m0 + r) * 512 + k0 + c * 8;
        size_t sbg = (size_t)(n0 + r) * 512 + k0 + c * 8;
        cpa16(d + A_OFF, g_xh + sa);
        cpa16(d + B_OFF, g_bh + sbg);
    }
    cpa_commit();
}

__global__ void __launch_bounds__(256, 2) k_gemm1_mma(const float* __restrict__ a_vec) {
    extern __shared__ char smem[];
    __shared__ float s_ad[2][64], s_as[2][64];
    uint32_t sb = smem_u32(smem);
    const int t = threadIdx.x;
    const int lane = t & 31, w = t >> 5;
    const int wm = w & 3, wn = w >> 2;
    const int m0 = blockIdx.x * 128, n0 = blockIdx.y * 128;

    if (t < 128) {
        int hh = t >> 6, j = t & 63;
        int gh = blockIdx.y * 2 + hh;
        s_ad[hh][j] = a_vec[gh * 128 + j];
        s_as[hh][j] = a_vec[gh * 128 + 64 + j];
    }

    float acc[2][8][4];
#pragma unroll
    for (int mf = 0; mf < 2; mf++)
#pragma unroll
        for (int nf = 0; nf < 8; nf++)
#pragma unroll
            for (int q = 0; q < 4; q++) acc[mf][nf][q] = 0.f;

    load_stage(sb, t, m0, n0, 0);

    const int a_row = wm * 32 + (lane & 15);
    const int a_colb = (lane >> 4) * 8;
    const int b_row = wn * 64 + ((lane >> 4) & 1) * 8 + (lane & 7);
    const int b_colb = ((lane >> 3) & 1) * 8;

    for (int kc = 0; kc < 16; kc++) {
        uint32_t s = sb + (uint32_t)(kc & 1) * STAGE;
        if (kc + 1 < 16) load_stage(sb + (uint32_t)((kc + 1) & 1) * STAGE, t, m0, n0, kc + 1);
        if (kc + 1 < 16) { cpa_wait<1>(); } else { cpa_wait<0>(); }
        __syncthreads();

#pragma unroll
        for (int ks = 0; ks < 2; ks++) {
            uint32_t ah[2][4];
#pragma unroll
            for (int mf = 0; mf < 2; mf++) {
                uint32_t ad = s + A_OFF +
                    (uint32_t)((a_row + mf * 16) * 80 + (ks * 16 + a_colb) * 2);
                ldm4(ah[mf], ad);
            }
#pragma unroll
            for (int nb = 0; nb < 4; nb++) {
                uint32_t bh4[4];
                uint32_t bd = s + B_OFF +
                    (uint32_t)((b_row + nb * 16) * 80 + (ks * 16 + b_colb) * 2);
                ldm4(bh4, bd);
#pragma unroll
                for (int mf = 0; mf < 2; mf++)
#pragma unroll
                    for (int half = 0; half < 2; half++) {
                        float* c = acc[mf][nb * 2 + half];
                        mma16816h(c, ah[mf], bh4[half * 2], bh4[half * 2 + 1]);
                    }
            }
        }
        __syncthreads();
    }

    // epilogue: store Wh (fp16) + fused f1 from fp32 accs
    const int ghead = blockIdx.y * 2 + wn;
#pragma unroll
    for (int mf = 0; mf < 2; mf++) {
        int rbase = m0 + wm * 32 + mf * 16 + (lane >> 2);
#pragma unroll
        for (int nf = 0; nf < 8; nf++) {
            int cc = n0 + wn * 64 + nf * 8 + (lane & 3) * 2;
            float* c = acc[mf][nf];
            if (rbase < Nn) {
                __half2 p;
                p.x = __float2half_rn(c[0]);
                p.y = __float2half_rn(c[1]);
                *(__half2*)(g_Whb + (size_t)rbase * 512 + cc) = p;
            }
            if (rbase + 8 < Nn) {
                __half2 p;
                p.x = __float2half_rn(c[2]);
                p.y = __float2half_rn(c[3]);
                *(__half2*)(g_Whb + (size_t)(rbase + 8) * 512 + cc) = p;
            }
        }
#pragma unroll
        for (int half = 0; half < 2; half++) {
            float pd = 0.f, ps = 0.f;
#pragma unroll
            for (int nf = 0; nf < 8; nf++) {
                int j0 = nf * 8 + (lane & 3) * 2;
                float c0 = acc[mf][nf][half * 2 + 0];
                float c1 = acc[mf][nf][half * 2 + 1];
                pd += c0 * s_ad[wn][j0] + c1 * s_ad[wn][j0 + 1];
                ps += c0 * s_as[wn][j0] + c1 * s_as[wn][j0 + 1];
            }
            pd += __shfl_xor_sync(0xffffffffu, pd, 1);
            pd += __shfl_xor_sync(0xffffffffu, pd, 2);
            ps += __shfl_xor_sync(0xffffffffu, ps, 1);
            ps += __shfl_xor_sync(0xffffffffu, ps, 2);
            int r = rbase + half * 8;
            if ((lane & 3) == 0 && r < Nn) {
                g_fd1[r * 8 + ghead] = pd;
                g_fs1[r * 8 + ghead] = ps;
            }
        }
    }
}

// ---------------- fp16 HMMA GEMM2 (+f2 epilogue), 2 CTAs/SM ----------------------
#define A2_OFF 0
#define B2_OFF 10240
#define STAGE2 15360
#define SMEM_GEMM2_TOTAL (2 * STAGE2)

__device__ __forceinline__ void load_stage2(uint32_t s, int t, int m0, int kc) {
    int k0 = kc * 32;
#pragma unroll
    for (int i = 0; i < 2; i++) {
        int idx = t + i * 256;
        int r = idx >> 2;
        int c = idx & 3;
        uint32_t d = s + (uint32_t)(r * 80 + c * 16);
        size_t sa = (size_t)(m0 + r) * 512 + k0 + c * 8;
        cpa16(d + A2_OFF, g_h1 + sa);
    }
    if (t < 256) {
        int r = t >> 2, c = t & 3;
        uint32_t d = s + (uint32_t)(r * 80 + c * 16);
        size_t sbg = (size_t)r * 512 + k0 + c * 8;
        cpa16(d + B2_OFF, g_b2 + sbg);
    }
    cpa_commit();
}

__global__ void __launch_bounds__(256, 2) k_gemm2_mma(const float* __restrict__ a_out) {
    extern __shared__ char smem[];
    __shared__ float s_a2d[64], s_a2s[64];
    __shared__ float s_pd[2][128], s_ps[2][128];
    uint32_t sb = smem_u32(smem);
    const int t = threadIdx.x;
    const int lane = t & 31, w = t >> 5;
    const int wm = w & 3, wn = w >> 2;
    const int m0 = blockIdx.x * 128;

    if (t < 64) {
        s_a2d[t] = a_out[t];
        s_a2s[t] = a_out[64 + t];
    }

    float acc[2][4][4];
#pragma unroll
    for (int mf = 0; mf < 2; mf++)
#pragma unroll
        for (int nf = 0; nf < 4; nf++)
#pragma unroll
            for (int q = 0; q < 4; q++) acc[mf][nf][q] = 0.f;

    load_stage2(sb, t, m0, 0);

    const int a_row = wm * 32 + (lane & 15);
    const int a_colb = (lane >> 4) * 8;
    const int b_row = wn * 32 + ((lane >> 4) & 1) * 8 + (lane & 7);
    const int b_colb = ((lane >> 3) & 1) * 8;

    for (int kc = 0; kc < 16; kc++) {
        uint32_t s = sb + (uint32_t)(kc & 1) * STAGE2;
        if (kc + 1 < 16) load_stage2(sb + (uint32_t)((kc + 1) & 1) * STAGE2, t, m0, kc + 1);
        if (kc + 1 < 16) { cpa_wait<1>(); } else { cpa_wait<0>(); }
        __syncthreads();

#pragma unroll
        for (int ks = 0; ks < 2; ks++) {
            uint32_t ah[2][4];
#pragma unroll
            for (int mf = 0; mf < 2; mf++) {
                uint32_t ad = s + A2_OFF +
                    (uint32_t)((a_row + mf * 16) * 80 + (ks * 16 + a_colb) * 2);
                ldm4(ah[mf], ad);
            }
#pragma unroll
            for (int nb = 0; nb < 2; nb++) {
                uint32_t bh4[4];
                uint32_t bd = s + B2_OFF +
                    (uint32_t)((b_row + nb * 16) * 80 + (ks * 16 + b_colb) * 2);
                ldm4(bh4, bd);
#pragma unroll
                for (int mf = 0; mf < 2; mf++)
#pragma unroll
                    for (int half = 0; half < 2; half++) {
                        float* c = acc[mf][nb * 2 + half];
                        mma16816h(c, ah[mf], bh4[half * 2], bh4[half * 2 + 1]);
                    }
            }
        }
        __syncthreads();
    }

#pragma unroll
    for (int mf = 0; mf < 2; mf++) {
        int rbase = m0 + wm * 32 + mf * 16 + (lane >> 2);
#pragma unroll
        for (int nf = 0; nf < 4; nf++) {
            int cc = wn * 32 + nf * 8 + (lane & 3) * 2;
            float* c = acc[mf][nf];
            if (rbase < Nn)
                *(float2*)(g_Wh2 + (size_t)rbase * 64 + cc) = make_float2(c[0], c[1]);
            if (rbase + 8 < Nn)
                *(float2*)(g_Wh2 + (size_t)(rbase + 8) * 64 + cc) = make_float2(c[2], c[3]);
        }
#pragma unroll
        for (int half = 0; half < 2; half++) {
            float pd = 0.f, ps = 0.f;
#pragma unroll
            for (int nf = 0; nf < 4; nf++) {
                int j0 = wn * 32 + nf * 8 + (lane & 3) * 2;
                float c0 = acc[mf][nf][half * 2 + 0];
                float c1 = acc[mf][nf][half * 2 + 1];
                pd += c0 * s_a2d[j0] + c1 * s_a2d[j0 + 1];
                ps += c0 * s_a2s[j0] + c1 * s_a2s[j0 + 1];
            }
            pd += __shfl_xor_sync(0xffffffffu, pd, 1);
            pd += __shfl_xor_sync(0xffffffffu, pd, 2);
            ps += __shfl_xor_sync(0xffffffffu, ps, 1);
            ps += __shfl_xor_sync(0xffffffffu, ps, 2);
            int rl = wm * 32 + mf * 16 + (lane >> 2) + half * 8;
            if ((lane & 3) == 0) {
                s_pd[wn][rl] = pd;
                s_ps[wn][rl] = ps;
            }
        }
    }
    __syncthreads();
    if (t < 128) {
        int r = m0 + t;
        if (r < Nn) {
            g_fd2[r] = s_pd[0][t] + s_pd[1][t];
            g_fs2[r] = s_ps[0][t] + s_ps[1][t];
        }
    }
}

// ---------------- CSR build ------------------------------------------------
__global__ void k_hist(const int* __restrict__ row) {
    int e = blockIdx.x * blockDim.x + threadIdx.x;
    if (e < Ee) atomicAdd(&g_cnt[row[e]], 1);
}

__global__ void k_scan() {   // 1024 threads, shfl-based
    __shared__ int s_w[32];
    __shared__ int s_base, s_next;
    int t = threadIdx.x, lane = t & 31, wid = t >> 5;
    if (t == 0) s_base = 0;
    __syncthreads();
    for (int start = 0; start < Nn; start += 1024) {
        int i = start + t;
        int v = (i < Nn) ? g_cnt[i] : 0;
        int sc = v;
#pragma unroll
        for (int d = 1; d < 32; d <<= 1) {
            int u = __shfl_up_sync(0xffffffffu, sc, d);
            if (lane >= d) sc += u;
        }
        if (lane == 31) s_w[wid] = sc;
        __syncthreads();
        if (wid == 0) {
            int wsc = s_w[lane];
#pragma unroll
            for (int d = 1; d < 32; d <<= 1) {
                int u = __shfl_up_sync(0xffffffffu, wsc, d);
                if (lane >= d) wsc += u;
            }
            s_w[lane] = wsc;
            if (lane == 31) s_next = wsc;
        }
        __syncthreads();
        int base = s_base;
        int warpoff = (wid == 0) ? 0 : s_w[wid - 1];
        int ex = base + warpoff + sc - v;
        if (i < Nn) { g_off[i] = ex; g_cur[i] = ex; }
        __syncthreads();
        if (t == 0) s_base = base + s_next;
        __syncthreads();
    }
    if (t == 0) g_off[Nn] = s_base;
}

__global__ void k_scatter(const int* __restrict__ row, const int* __restrict__ col) {
    int e = blockIdx.x * blockDim.x + threadIdx.x;
    if (e < Ee) {
        int r = row[e];
        int p = atomicAdd(&g_cur[r], 1);
        g_pos[e]  = p;
        g_cols[p] = col[e];
    }
}

// ---------------- layer1: edge logits -> CSR slots --------------------------
__global__ void k_logits1(const int* __restrict__ row, const int* __restrict__ col) {
    int e = blockIdx.x * blockDim.x + threadIdx.x;
    if (e >= Ee) return;
    int r = row[e], c = col[e];
    float4 d0 = *(const float4*)(g_fd1 + r * 8);
    float4 d1 = *(const float4*)(g_fd1 + r * 8 + 4);
    float4 s0 = *(const float4*)(g_fs1 + c * 8);
    float4 s1 = *(const float4*)(g_fs1 + c * 8 + 4);
    float v[8] = {d0.x + s0.x, d0.y + s0.y, d0.z + s0.z, d0.w + s0.w,
                  d1.x + s1.x, d1.y + s1.y, d1.z + s1.z, d1.w + s1.w};
#pragma unroll
    for (int h = 0; h < 8; h++) v[h] = v[h] > 0.f ? v[h] : ALPHA * v[h];
    size_t p = (size_t)g_pos[e] * 8;
    *(float4*)(g_lg1 + p)     = make_float4(v[0], v[1], v[2], v[3]);
    *(float4*)(g_lg1 + p + 4) = make_float4(v[4], v[5], v[6], v[7]);
}

// ---------------- layer1: fused softmax stats + fp16 gather agg + ELU --------
__global__ void __launch_bounds__(256) k_agg1() {
    int i = blockIdx.x;
    int t = threadIdx.x;
    int o = g_off[i], oe = g_off[i + 1];
    __shared__ float s_red[32][8];
    __shared__ float s_mx[8], s_iv[8];
    __shared__ float s_att[32][8];
    __shared__ int   s_col[32];
    int j = t >> 3, h = t & 7;

    float mx = -3.4e38f;
    for (int p = o + j; p < oe; p += 32)
        mx = fmaxf(mx, g_lg1[(size_t)p * 8 + h]);
    s_red[j][h] = mx;
    __syncthreads();
#pragma unroll
    for (int s = 16; s > 0; s >>= 1) {
        if (j < s) s_red[j][h] = fmaxf(s_red[j][h], s_red[j + s][h]);
        __syncthreads();
    }
    float mxh = s_red[0][h];
    __syncthreads();
    float sm = 0.f;
    for (int p = o + j; p < oe; p += 32)
        sm += __expf(g_lg1[(size_t)p * 8 + h] - mxh);
    s_red[j][h] = sm;
    __syncthreads();
#pragma unroll
    for (int s = 16; s > 0; s >>= 1) {
        if (j < s) s_red[j][h] += s_red[j + s][h];
        __syncthreads();
    }
    if (j == 0) {
        s_mx[h] = (oe > o) ? mxh : 0.f;
        s_iv[h] = (oe > o) ? 1.f / fmaxf(s_red[0][h], 1e-16f) : 0.f;
    }
    __syncthreads();

    // each thread handles dims (2t, 2t+1); head = t>>5
    int ha = t >> 5;
    float acc0 = 0.f, acc1 = 0.f;
    for (int base = o; base < oe; base += 32) {
        int cnt = min(32, oe - base);
        __syncthreads();
        if (j < cnt)
            s_att[j][h] = __expf(g_lg1[(size_t)(base + j) * 8 + h] - s_mx[h]) * s_iv[h];
        if (t < cnt) s_col[t] = g_cols[base + t];
        __syncthreads();
        for (int q = 0; q < cnt; q++) {
            int c = s_col[q];
            const __half2* whc = (const __half2*)(g_Whb + (size_t)c * 512);
            float2 v = __half22float2(whc[t]);
            float wv = s_att[q][ha];
            acc0 = fmaf(wv, v.x, acc0);
            acc1 = fmaf(wv, v.y, acc1);
        }
    }
    float v0 = acc0 > 0.f ? acc0 : (__expf(acc0) - 1.f);
    float v1 = acc1 > 0.f ? acc1 : (__expf(acc1) - 1.f);
    __half2 p;
    p.x = __float2half_rn(v0);
    p.y = __float2half_rn(v1);
    *(__half2*)(g_h1 + (size_t)i * 512 + 2 * t) = p;
}

// ---------------- layer2: edge logits ---------------------------------------
__global__ void k_logits2(const int* __restrict__ row, const int* __restrict__ col) {
    int e = blockIdx.x * blockDim.x + threadIdx.x;
    if (e >= Ee) return;
    float v = g_fd2[row[e]] + g_fs2[col[e]];
    g_lg2[g_pos[e]] = v > 0.f ? v : ALPHA * v;
}

// ---------------- layer2: fused stats + aggregation --------------------------
__global__ void __launch_bounds__(64) k_agg2(float* __restrict__ out) {
    int i = blockIdx.x;
    int t = threadIdx.x;  // 64
    int o = g_off[i], oe = g_off[i + 1];
    __shared__ float s_r[64];
    __shared__ float s_att[64];
    __shared__ int   s_col[64];

    float mx = -3.4e38f;
    for (int p = o + t; p < oe; p += 64) mx = fmaxf(mx, g_lg2[p]);
    s_r[t] = mx;
    __syncthreads();
#pragma unroll
    for (int s = 32; s > 0; s >>= 1) {
        if (t < s) s_r[t] = fmaxf(s_r[t], s_r[t + s]);
        __syncthreads();
    }
    float M = s_r[0];
    __syncthreads();
    float sm = 0.f;
    for (int p = o + t; p < oe; p += 64) sm += __expf(g_lg2[p] - M);
    s_r[t] = sm;
    __syncthreads();
#pragma unroll
    for (int s = 32; s > 0; s >>= 1) {
        if (t < s) s_r[t] += s_r[t + s];
        __syncthreads();
    }
    float iv = (oe > o) ? 1.f / fmaxf(s_r[0], 1e-16f) : 0.f;
    __syncthreads();

    float acc = 0.f;
    for (int base = o; base < oe; base += 64) {
        int cnt = min(64, oe - base);
        __syncthreads();
        if (t < cnt) {
            s_att[t] = __expf(g_lg2[base + t] - M) * iv;
            s_col[t] = g_cols[base + t];
        }
        __syncthreads();
        for (int q = 0; q < cnt; q++)
            acc = fmaf(s_att[q], g_Wh2[(size_t)s_col[q] * 64 + t], acc);
    }
    out[(size_t)i * 64 + t] = acc;
}

// ---------------- launch -----------------------------------------------------
extern "C" void kernel_launch(void* const* d_in, const int* in_sizes, int n_in,
                              void* d_out, int out_size) {
    const float* x     = (const float*)d_in[0];
    const int*   row   = (const int*)  d_in[1];
    const int*   col   = (const int*)  d_in[2];
    const float* W     = (const float*)d_in[3];
    const float* a     = (const float*)d_in[4];
    const float* W_out = (const float*)d_in[5];
    const float* a_out = (const float*)d_in[6];
    float* out = (float*)d_out;

    const int EB = (Ee + 255) / 256;

    cudaFuncSetAttribute(k_gemm1_mma, cudaFuncAttributeMaxDynamicSharedMemorySize,
                         SMEM_GEMM_TOTAL);
    cudaFuncSetAttribute(k_gemm2_mma, cudaFuncAttributeMaxDynamicSharedMemorySize,
                         SMEM_GEMM2_TOTAL);

    k_cvt_x<<<(int)(((long long)Mpad * 128 + 255) / 256), 256>>>(x);       // 0
    k_init_misc<<<(512 * 512 + 255) / 256, 256>>>(W, W_out);               // 1
    k_hist<<<EB, 256>>>(row);                                              // 2
    k_gemm1_mma<<<dim3(Mpad / 128, 4), 256, SMEM_GEMM_TOTAL>>>(a);         // 3 <- profiled
    k_scan<<<1, 1024>>>();                                                 // 4
    k_scatter<<<EB, 256>>>(row, col);                                      // 5
    k_logits1<<<EB, 256>>>(row, col);                                      // 6
    k_agg1<<<Nn, 256>>>();                                                 // 7
    k_gemm2_mma<<<Mpad / 128, 256, SMEM_GEMM2_TOTAL>>>(a_out);             // 8
    k_logits2<<<EB, 256>>>(row, col);                                      // 9
    k_agg2<<<Nn, 64>>>(out);                                               // 10
}

// round 14
// speedup vs baseline: 1.5700x; 1.0508x over previous
#include <cuda_runtime.h>
#include <cuda_bf16.h>
#include <cuda_fp16.h>
#include <stdint.h>
#include <math.h>

// Problem constants
#define Nn    50000
#define Mpad  50048
#define Ee    800000
#define FEAT  512
#define HEADS 8
#define HID   64
#define C1    512
#define NC    64
#define ALPHA 0.2f

// ---------------- scratch -----------------------------------------------------
__device__ float g_fd1[Nn * HEADS];
__device__ float g_fs1[Nn * HEADS];
__device__ float g_fd2[Nn];
__device__ float g_fs2[Nn];
__device__ int   g_cnt[Nn];
__device__ int   g_off[Nn + 1];
__device__ int   g_cur[Nn];
__device__ int   g_cols[Ee];

// fp16 operands / intermediates
__device__ __align__(256) __half g_xh [(size_t)Mpad * 512];   // x in fp16
__device__ __align__(256) __half g_bh [512 * 512];            // W1t in fp16
__device__ __align__(256) __half g_Whb[(size_t)Nn * 512];     // layer1 Wh in fp16
__device__ __align__(256) __half g_h1 [(size_t)Mpad * 512];   // h1 fp16 (pad rows stay 0)
__device__ __align__(256) __half g_b2 [64 * 512];             // W_out_t in fp16
__device__ __align__(256) __half g_Wh2h[(size_t)Nn * 64];     // layer2 Wh in fp16

// ---------------- PTX helpers --------------------------------------------------
__device__ __forceinline__ uint32_t smem_u32(const void* p) {
    uint32_t a;
    asm("{ .reg .u64 t; cvta.to.shared.u64 t, %1; cvt.u32.u64 %0, t; }" : "=r"(a) : "l"(p));
    return a;
}
__device__ __forceinline__ void cpa16(uint32_t dst, const void* src) {
    asm volatile("cp.async.cg.shared.global [%0], [%1], 16;" :: "r"(dst), "l"(src));
}
__device__ __forceinline__ void cpa_commit() {
    asm volatile("cp.async.commit_group;" ::: "memory");
}
template <int N> __device__ __forceinline__ void cpa_wait() {
    asm volatile("cp.async.wait_group %0;" :: "n"(N) : "memory");
}
__device__ __forceinline__ void ldm4(uint32_t* r, uint32_t addr) {
    asm volatile("ldmatrix.sync.aligned.m8n8.x4.shared.b16 {%0,%1,%2,%3}, [%4];"
                 : "=r"(r[0]), "=r"(r[1]), "=r"(r[2]), "=r"(r[3]) : "r"(addr));
}
__device__ __forceinline__ void mma16816h(float* c, const uint32_t* a,
                                          uint32_t b0, uint32_t b1) {
    asm volatile(
        "mma.sync.aligned.m16n8k16.row.col.f32.f16.f16.f32 "
        "{%0,%1,%2,%3}, {%4,%5,%6,%7}, {%8,%9}, {%0,%1,%2,%3};"
        : "+f"(c[0]), "+f"(c[1]), "+f"(c[2]), "+f"(c[3])
        : "r"(a[0]), "r"(a[1]), "r"(a[2]), "r"(a[3]), "r"(b0), "r"(b1));
}

// ---------------- conversion / init kernels -------------------------------------
__global__ void k_cvt_x(const float* __restrict__ x) {
    long long i4 = (long long)blockIdx.x * blockDim.x + threadIdx.x;
    if (i4 >= (long long)Mpad * 128) return;
    long long row = i4 >> 7;
    float4 v = make_float4(0.f, 0.f, 0.f, 0.f);
    if (row < Nn) v = ((const float4*)x)[i4];
    __half2 p0, p1;
    p0.x = __float2half_rn(v.x); p0.y = __float2half_rn(v.y);
    p1.x = __float2half_rn(v.z); p1.y = __float2half_rn(v.w);
    *(__half2*)(g_xh + i4 * 4)     = p0;
    *(__half2*)(g_xh + i4 * 4 + 2) = p1;
}

__global__ void k_init_misc(const float* __restrict__ W,
                            const float* __restrict__ W_out) {
    int idx = blockIdx.x * blockDim.x + threadIdx.x;
    if (idx < 512 * 512) {
        int n = idx >> 9, k = idx & 511;
        float v = W[(size_t)(n >> 6) * (512 * 64) + (size_t)k * 64 + (n & 63)];
        g_bh[idx] = __float2half_rn(v);
    }
    if (idx < 64 * 512) {
        int n = idx >> 9, k = idx & 511;
        g_b2[idx] = __float2half_rn(W_out[(size_t)k * 64 + n]);
    }
    if (idx < Nn) g_cnt[idx] = 0;
}

// ---------------- fp16 HMMA GEMM1 (+f1 epilogue), 2 CTAs/SM ----------------------
#define A_OFF 0
#define B_OFF 10240
#define STAGE 20480
#define SMEM_GEMM_TOTAL (2 * STAGE)

__device__ __forceinline__ void load_stage(uint32_t s, int t, int m0, int n0, int kc) {
    int k0 = kc * 32;
#pragma unroll
    for (int i = 0; i < 2; i++) {
        int idx = t + i * 256;
        int r = idx >> 2;
        int c = idx & 3;
        uint32_t d = s + (uint32_t)(r * 80 + c * 16);
        size_t sa = (size_t)(m0 + r) * 512 + k0 + c * 8;
        size_t sbg = (size_t)(n0 + r) * 512 + k0 + c * 8;
        cpa16(d + A_OFF, g_xh + sa);
        cpa16(d + B_OFF, g_bh + sbg);
    }
    cpa_commit();
}

__global__ void __launch_bounds__(256, 2) k_gemm1_mma(const float* __restrict__ a_vec) {
    extern __shared__ char smem[];
    __shared__ float s_ad[2][64], s_as[2][64];
    uint32_t sb = smem_u32(smem);
    const int t = threadIdx.x;
    const int lane = t & 31, w = t >> 5;
    const int wm = w & 3, wn = w >> 2;
    const int m0 = blockIdx.x * 128, n0 = blockIdx.y * 128;

    if (t < 128) {
        int hh = t >> 6, j = t & 63;
        int gh = blockIdx.y * 2 + hh;
        s_ad[hh][j] = a_vec[gh * 128 + j];
        s_as[hh][j] = a_vec[gh * 128 + 64 + j];
    }

    float acc[2][8][4];
#pragma unroll
    for (int mf = 0; mf < 2; mf++)
#pragma unroll
        for (int nf = 0; nf < 8; nf++)
#pragma unroll
            for (int q = 0; q < 4; q++) acc[mf][nf][q] = 0.f;

    load_stage(sb, t, m0, n0, 0);

    const int a_row = wm * 32 + (lane & 15);
    const int a_colb = (lane >> 4) * 8;
    const int b_row = wn * 64 + ((lane >> 4) & 1) * 8 + (lane & 7);
    const int b_colb = ((lane >> 3) & 1) * 8;

    for (int kc = 0; kc < 16; kc++) {
        uint32_t s = sb + (uint32_t)(kc & 1) * STAGE;
        if (kc + 1 < 16) load_stage(sb + (uint32_t)((kc + 1) & 1) * STAGE, t, m0, n0, kc + 1);
        if (kc + 1 < 16) { cpa_wait<1>(); } else { cpa_wait<0>(); }
        __syncthreads();

#pragma unroll
        for (int ks = 0; ks < 2; ks++) {
            uint32_t ah[2][4];
#pragma unroll
            for (int mf = 0; mf < 2; mf++) {
                uint32_t ad = s + A_OFF +
                    (uint32_t)((a_row + mf * 16) * 80 + (ks * 16 + a_colb) * 2);
                ldm4(ah[mf], ad);
            }
#pragma unroll
            for (int nb = 0; nb < 4; nb++) {
                uint32_t bh4[4];
                uint32_t bd = s + B_OFF +
                    (uint32_t)((b_row + nb * 16) * 80 + (ks * 16 + b_colb) * 2);
                ldm4(bh4, bd);
#pragma unroll
                for (int mf = 0; mf < 2; mf++)
#pragma unroll
                    for (int half = 0; half < 2; half++) {
                        float* c = acc[mf][nb * 2 + half];
                        mma16816h(c, ah[mf], bh4[half * 2], bh4[half * 2 + 1]);
                    }
            }
        }
        __syncthreads();
    }

    const int ghead = blockIdx.y * 2 + wn;
#pragma unroll
    for (int mf = 0; mf < 2; mf++) {
        int rbase = m0 + wm * 32 + mf * 16 + (lane >> 2);
#pragma unroll
        for (int nf = 0; nf < 8; nf++) {
            int cc = n0 + wn * 64 + nf * 8 + (lane & 3) * 2;
            float* c = acc[mf][nf];
            if (rbase < Nn) {
                __half2 p;
                p.x = __float2half_rn(c[0]);
                p.y = __float2half_rn(c[1]);
                *(__half2*)(g_Whb + (size_t)rbase * 512 + cc) = p;
            }
            if (rbase + 8 < Nn) {
                __half2 p;
                p.x = __float2half_rn(c[2]);
                p.y = __float2half_rn(c[3]);
                *(__half2*)(g_Whb + (size_t)(rbase + 8) * 512 + cc) = p;
            }
        }
#pragma unroll
        for (int half = 0; half < 2; half++) {
            float pd = 0.f, ps = 0.f;
#pragma unroll
            for (int nf = 0; nf < 8; nf++) {
                int j0 = nf * 8 + (lane & 3) * 2;
                float c0 = acc[mf][nf][half * 2 + 0];
                float c1 = acc[mf][nf][half * 2 + 1];
                pd += c0 * s_ad[wn][j0] + c1 * s_ad[wn][j0 + 1];
                ps += c0 * s_as[wn][j0] + c1 * s_as[wn][j0 + 1];
            }
            pd += __shfl_xor_sync(0xffffffffu, pd, 1);
            pd += __shfl_xor_sync(0xffffffffu, pd, 2);
            ps += __shfl_xor_sync(0xffffffffu, ps, 1);
            ps += __shfl_xor_sync(0xffffffffu, ps, 2);
            int r = rbase + half * 8;
            if ((lane & 3) == 0 && r < Nn) {
                g_fd1[r * 8 + ghead] = pd;
                g_fs1[r * 8 + ghead] = ps;
            }
        }
    }
}

// ---------------- fp16 HMMA GEMM2 (+f2 epilogue), 2 CTAs/SM ----------------------
#define A2_OFF 0
#define B2_OFF 10240
#define STAGE2 15360
#define SMEM_GEMM2_TOTAL (2 * STAGE2)

__device__ __forceinline__ void load_stage2(uint32_t s, int t, int m0, int kc) {
    int k0 = kc * 32;
#pragma unroll
    for (int i = 0; i < 2; i++) {
        int idx = t + i * 256;
        int r = idx >> 2;
        int c = idx & 3;
        uint32_t d = s + (uint32_t)(r * 80 + c * 16);
        size_t sa = (size_t)(m0 + r) * 512 + k0 + c * 8;
        cpa16(d + A2_OFF, g_h1 + sa);
    }
    if (t < 256) {
        int r = t >> 2, c = t & 3;
        uint32_t d = s + (uint32_t)(r * 80 + c * 16);
        size_t sbg = (size_t)r * 512 + k0 + c * 8;
        cpa16(d + B2_OFF, g_b2 + sbg);
    }
    cpa_commit();
}

__global__ void __launch_bounds__(256, 2) k_gemm2_mma(const float* __restrict__ a_out) {
    extern __shared__ char smem[];
    __shared__ float s_a2d[64], s_a2s[64];
    __shared__ float s_pd[2][128], s_ps[2][128];
    uint32_t sb = smem_u32(smem);
    const int t = threadIdx.x;
    const int lane = t & 31, w = t >> 5;
    const int wm = w & 3, wn = w >> 2;
    const int m0 = blockIdx.x * 128;

    if (t < 64) {
        s_a2d[t] = a_out[t];
        s_a2s[t] = a_out[64 + t];
    }

    float acc[2][4][4];
#pragma unroll
    for (int mf = 0; mf < 2; mf++)
#pragma unroll
        for (int nf = 0; nf < 4; nf++)
#pragma unroll
            for (int q = 0; q < 4; q++) acc[mf][nf][q] = 0.f;

    load_stage2(sb, t, m0, 0);

    const int a_row = wm * 32 + (lane & 15);
    const int a_colb = (lane >> 4) * 8;
    const int b_row = wn * 32 + ((lane >> 4) & 1) * 8 + (lane & 7);
    const int b_colb = ((lane >> 3) & 1) * 8;

    for (int kc = 0; kc < 16; kc++) {
        uint32_t s = sb + (uint32_t)(kc & 1) * STAGE2;
        if (kc + 1 < 16) load_stage2(sb + (uint32_t)((kc + 1) & 1) * STAGE2, t, m0, kc + 1);
        if (kc + 1 < 16) { cpa_wait<1>(); } else { cpa_wait<0>(); }
        __syncthreads();

#pragma unroll
        for (int ks = 0; ks < 2; ks++) {
            uint32_t ah[2][4];
#pragma unroll
            for (int mf = 0; mf < 2; mf++) {
                uint32_t ad = s + A2_OFF +
                    (uint32_t)((a_row + mf * 16) * 80 + (ks * 16 + a_colb) * 2);
                ldm4(ah[mf], ad);
            }
#pragma unroll
            for (int nb = 0; nb < 2; nb++) {
                uint32_t bh4[4];
                uint32_t bd = s + B2_OFF +
                    (uint32_t)((b_row + nb * 16) * 80 + (ks * 16 + b_colb) * 2);
                ldm4(bh4, bd);
#pragma unroll
                for (int mf = 0; mf < 2; mf++)
#pragma unroll
                    for (int half = 0; half < 2; half++) {
                        float* c = acc[mf][nb * 2 + half];
                        mma16816h(c, ah[mf], bh4[half * 2], bh4[half * 2 + 1]);
                    }
            }
        }
        __syncthreads();
    }

#pragma unroll
    for (int mf = 0; mf < 2; mf++) {
        int rbase = m0 + wm * 32 + mf * 16 + (lane >> 2);
#pragma unroll
        for (int nf = 0; nf < 4; nf++) {
            int cc = wn * 32 + nf * 8 + (lane & 3) * 2;
            float* c = acc[mf][nf];
            if (rbase < Nn) {
                __half2 p;
                p.x = __float2half_rn(c[0]);
                p.y = __float2half_rn(c[1]);
                *(__half2*)(g_Wh2h + (size_t)rbase * 64 + cc) = p;
            }
            if (rbase + 8 < Nn) {
                __half2 p;
                p.x = __float2half_rn(c[2]);
                p.y = __float2half_rn(c[3]);
                *(__half2*)(g_Wh2h + (size_t)(rbase + 8) * 64 + cc) = p;
            }
        }
#pragma unroll
        for (int half = 0; half < 2; half++) {
            float pd = 0.f, ps = 0.f;
#pragma unroll
            for (int nf = 0; nf < 4; nf++) {
                int j0 = wn * 32 + nf * 8 + (lane & 3) * 2;
                float c0 = acc[mf][nf][half * 2 + 0];
                float c1 = acc[mf][nf][half * 2 + 1];
                pd += c0 * s_a2d[j0] + c1 * s_a2d[j0 + 1];
                ps += c0 * s_a2s[j0] + c1 * s_a2s[j0 + 1];
            }
            pd += __shfl_xor_sync(0xffffffffu, pd, 1);
            pd += __shfl_xor_sync(0xffffffffu, pd, 2);
            ps += __shfl_xor_sync(0xffffffffu, ps, 1);
            ps += __shfl_xor_sync(0xffffffffu, ps, 2);
            int rl = wm * 32 + mf * 16 + (lane >> 2) + half * 8;
            if ((lane & 3) == 0) {
                s_pd[wn][rl] = pd;
                s_ps[wn][rl] = ps;
            }
        }
    }
    __syncthreads();
    if (t < 128) {
        int r = m0 + t;
        if (r < Nn) {
            g_fd2[r] = s_pd[0][t] + s_pd[1][t];
            g_fs2[r] = s_ps[0][t] + s_ps[1][t];
        }
    }
}

// ---------------- CSR build ------------------------------------------------
__global__ void k_hist(const int* __restrict__ row) {
    int e = blockIdx.x * blockDim.x + threadIdx.x;
    if (e < Ee) atomicAdd(&g_cnt[row[e]], 1);
}

__global__ void k_scan() {
    __shared__ int s_w[32];
    __shared__ int s_base, s_next;
    int t = threadIdx.x, lane = t & 31, wid = t >> 5;
    if (t == 0) s_base = 0;
    __syncthreads();
    for (int start = 0; start < Nn; start += 1024) {
        int i = start + t;
        int v = (i < Nn) ? g_cnt[i] : 0;
        int sc = v;
#pragma unroll
        for (int d = 1; d < 32; d <<= 1) {
            int u = __shfl_up_sync(0xffffffffu, sc, d);
            if (lane >= d) sc += u;
        }
        if (lane == 31) s_w[wid] = sc;
        __syncthreads();
        if (wid == 0) {
            int wsc = s_w[lane];
#pragma unroll
            for (int d = 1; d < 32; d <<= 1) {
                int u = __shfl_up_sync(0xffffffffu, wsc, d);
                if (lane >= d) wsc += u;
            }
            s_w[lane] = wsc;
            if (lane == 31) s_next = wsc;
        }
        __syncthreads();
        int base = s_base;
        int warpoff = (wid == 0) ? 0 : s_w[wid - 1];
        int ex = base + warpoff + sc - v;
        if (i < Nn) { g_off[i] = ex; g_cur[i] = ex; }
        __syncthreads();
        if (t == 0) s_base = base + s_next;
        __syncthreads();
    }
    if (t == 0) g_off[Nn] = s_base;
}

__global__ void k_scatter(const int* __restrict__ row, const int* __restrict__ col) {
    int e = blockIdx.x * blockDim.x + threadIdx.x;
    if (e < Ee) {
        int p = atomicAdd(&g_cur[row[e]], 1);
        g_cols[p] = col[e];
    }
}

// ---------------- layer1: fused logits + softmax + fp16 gather agg + ELU -----
__global__ void __launch_bounds__(256) k_agg1() {
    int i = blockIdx.x;
    int t = threadIdx.x;
    int o = g_off[i], oe = g_off[i + 1];
    __shared__ float s_red[32][8];
    __shared__ float s_mx[8], s_iv[8];
    __shared__ float s_att[32][8];
    __shared__ int   s_col[32];
    __shared__ float s_fd[8];
    int j = t >> 3, h = t & 7;

    if (t < 8) s_fd[t] = g_fd1[i * 8 + t];
    __syncthreads();
    float fdh = s_fd[h];

    // pass 1: max of lrelu(fd + fs[col])
    float mx = -3.4e38f;
    for (int p = o + j; p < oe; p += 32) {
        int c = g_cols[p];
        float v = fdh + g_fs1[c * 8 + h];
        v = v > 0.f ? v : ALPHA * v;
        mx = fmaxf(mx, v);
    }
    s_red[j][h] = mx;
    __syncthreads();
#pragma unroll
    for (int s = 16; s > 0; s >>= 1) {
        if (j < s) s_red[j][h] = fmaxf(s_red[j][h], s_red[j + s][h]);
        __syncthreads();
    }
    float mxh = s_red[0][h];
    __syncthreads();

    // pass 2: sum of exp
    float sm = 0.f;
    for (int p = o + j; p < oe; p += 32) {
        int c = g_cols[p];
        float v = fdh + g_fs1[c * 8 + h];
        v = v > 0.f ? v : ALPHA * v;
        sm += __expf(v - mxh);
    }
    s_red[j][h] = sm;
    __syncthreads();
#pragma unroll
    for (int s = 16; s > 0; s >>= 1) {
        if (j < s) s_red[j][h] += s_red[j + s][h];
        __syncthreads();
    }
    if (j == 0) {
        s_mx[h] = (oe > o) ? mxh : 0.f;
        s_iv[h] = (oe > o) ? 1.f / fmaxf(s_red[0][h], 1e-16f) : 0.f;
    }
    __syncthreads();

    // pass 3: chunked aggregation; dims (2t, 2t+1); head = t>>5
    int ha = t >> 5;
    float acc0 = 0.f, acc1 = 0.f;
    for (int base = o; base < oe; base += 32) {
        int cnt = min(32, oe - base);
        __syncthreads();
        if (j < cnt) {
            int c = g_cols[base + j];
            float v = fdh + g_fs1[c * 8 + h];
            v = v > 0.f ? v : ALPHA * v;
            s_att[j][h] = __expf(v - s_mx[h]) * s_iv[h];
        }
        if (t < cnt) s_col[t] = g_cols[base + t];
        __syncthreads();
        for (int q = 0; q < cnt; q++) {
            int c = s_col[q];
            const __half2* whc = (const __half2*)(g_Whb + (size_t)c * 512);
            float2 v = __half22float2(whc[t]);
            float wv = s_att[q][ha];
            acc0 = fmaf(wv, v.x, acc0);
            acc1 = fmaf(wv, v.y, acc1);
        }
    }
    float v0 = acc0 > 0.f ? acc0 : (__expf(acc0) - 1.f);
    float v1 = acc1 > 0.f ? acc1 : (__expf(acc1) - 1.f);
    __half2 p;
    p.x = __float2half_rn(v0);
    p.y = __float2half_rn(v1);
    *(__half2*)(g_h1 + (size_t)i * 512 + 2 * t) = p;
}

// ---------------- layer2: fused logits + softmax + aggregation ---------------
__global__ void __launch_bounds__(64) k_agg2(float* __restrict__ out) {
    int i = blockIdx.x;
    int t = threadIdx.x;  // 64
    int o = g_off[i], oe = g_off[i + 1];
    __shared__ float s_r[64];
    __shared__ float s_att[64];
    __shared__ int   s_col[64];
    float fd = g_fd2[i];

    float mx = -3.4e38f;
    for (int p = o + t; p < oe; p += 64) {
        float v = fd + g_fs2[g_cols[p]];
        v = v > 0.f ? v : ALPHA * v;
        mx = fmaxf(mx, v);
    }
    s_r[t] = mx;
    __syncthreads();
#pragma unroll
    for (int s = 32; s > 0; s >>= 1) {
        if (t < s) s_r[t] = fmaxf(s_r[t], s_r[t + s]);
        __syncthreads();
    }
    float M = s_r[0];
    __syncthreads();
    float sm = 0.f;
    for (int p = o + t; p < oe; p += 64) {
        float v = fd + g_fs2[g_cols[p]];
        v = v > 0.f ? v : ALPHA * v;
        sm += __expf(v - M);
    }
    s_r[t] = sm;
    __syncthreads();
#pragma unroll
    for (int s = 32; s > 0; s >>= 1) {
        if (t < s) s_r[t] += s_r[t + s];
        __syncthreads();
    }
    float iv = (oe > o) ? 1.f / fmaxf(s_r[0], 1e-16f) : 0.f;
    __syncthreads();

    float acc = 0.f;
    for (int base = o; base < oe; base += 64) {
        int cnt = min(64, oe - base);
        __syncthreads();
        if (t < cnt) {
            int c = g_cols[base + t];
            float v = fd + g_fs2[c];
            v = v > 0.f ? v : ALPHA * v;
            s_att[t] = __expf(v - M) * iv;
            s_col[t] = c;
        }
        __syncthreads();
        for (int q = 0; q < cnt; q++)
            acc = fmaf(s_att[q], __half2float(g_Wh2h[(size_t)s_col[q] * 64 + t]), acc);
    }
    out[(size_t)i * 64 + t] = acc;
}

// ---------------- launch -----------------------------------------------------
extern "C" void kernel_launch(void* const* d_in, const int* in_sizes, int n_in,
                              void* d_out, int out_size) {
    const float* x     = (const float*)d_in[0];
    const int*   row   = (const int*)  d_in[1];
    const int*   col   = (const int*)  d_in[2];
    const float* W     = (const float*)d_in[3];
    const float* a     = (const float*)d_in[4];
    const float* W_out = (const float*)d_in[5];
    const float* a_out = (const float*)d_in[6];
    float* out = (float*)d_out;

    const int EB = (Ee + 255) / 256;

    cudaFuncSetAttribute(k_gemm1_mma, cudaFuncAttributeMaxDynamicSharedMemorySize,
                         SMEM_GEMM_TOTAL);
    cudaFuncSetAttribute(k_gemm2_mma, cudaFuncAttributeMaxDynamicSharedMemorySize,
                         SMEM_GEMM2_TOTAL);

    k_cvt_x<<<(int)(((long long)Mpad * 128 + 255) / 256), 256>>>(x);       // 0
    k_init_misc<<<(512 * 512 + 255) / 256, 256>>>(W, W_out);               // 1
    k_hist<<<EB, 256>>>(row);                                              // 2
    k_gemm1_mma<<<dim3(Mpad / 128, 4), 256, SMEM_GEMM_TOTAL>>>(a);         // 3 <- profiled
    k_scan<<<1, 1024>>>();                                                 // 4
    k_scatter<<<EB, 256>>>(row, col);                                      // 5
    k_agg1<<<Nn, 256>>>();                                                 // 6
    k_gemm2_mma<<<Mpad / 128, 256, SMEM_GEMM2_TOTAL>>>(a_out);             // 7
    k_agg2<<<Nn, 64>>>(out);                                               // 8
}